// round 13
// baseline (speedup 1.0000x reference)
#include <cuda_runtime.h>
#include <math.h>

#define Nn 50000
#define Ee 400000
#define NBLK 196   // ceil(Nn/256)

// output packing: out[N*4], nh[N*64], nc[N*64], eh[E*32], ec[E*32]
#define OUT_OFF 0
#define NH_OFF  (Nn*4)
#define NC_OFF  (NH_OFF + Nn*64)
#define EH_OFF  (NC_OFF + Nn*64)
#define EC_OFF  (EH_OFF + Ee*32)

// ---------------- scratch ----------------
__device__ int   g_cnti[Nn];
__device__ int   g_bsum[256];
__device__ int   g_boff[256];
__device__ int   g_off[Nn+1];
__device__ int   g_cursor[Nn];
__device__ int   g_eid[Ee];
__device__ int   g_esrc[Ee];
__device__ float g_cntf[Nn];
__device__ float g_xcat[Nn*96];
__device__ float g_xh[Nn*256];
__device__ float g_as[Nn*4];
__device__ float g_ad[Nn*4];
__device__ float g_xgat[Nn*64];
__device__ float g_P[Nn*64];
__device__ float g_Q[Nn*64];
__device__ float g_elat[Ee*32];
__device__ float g_agg[Nn*32];

typedef unsigned long long u64;
__device__ __forceinline__ u64 pk2(float lo, float hi){ u64 r; asm("mov.b64 %0, {%1,%2};" : "=l"(r) : "f"(lo), "f"(hi)); return r; }
__device__ __forceinline__ u64 dup2(float v){ return pk2(v,v); }
__device__ __forceinline__ void fma2(u64 &acc, u64 a, u64 b){ asm("fma.rn.f32x2 %0, %1, %2, %0;" : "+l"(acc) : "l"(a), "l"(b)); }
__device__ __forceinline__ void up2(u64 v, float &lo, float &hi){ asm("mov.b64 {%0,%1}, %2;" : "=f"(lo), "=f"(hi) : "l"(v)); }

__device__ __forceinline__ float tanha(float x){ float r; asm("tanh.approx.f32 %0, %1;" : "=f"(r) : "f"(x)); return r; }
__device__ __forceinline__ float fsig(float x){ return fmaf(0.5f, tanha(0.5f*x), 0.5f); }
__device__ __forceinline__ float leaky(float x){ return x > 0.f ? x : 0.2f*x; }

// ================= CSR build =================
__global__ void k_zero_cnt(){
    int t = blockIdx.x*blockDim.x + threadIdx.x;
    if (t < Nn) g_cnti[t] = 0;
}
__global__ void k_count(const int* __restrict__ ei){
    int e = blockIdx.x*blockDim.x + threadIdx.x;
    if (e < Ee) atomicAdd(&g_cnti[ei[Ee+e]], 1);
}
__global__ void k_scan1(){
    __shared__ int s[256];
    int i = blockIdx.x*256 + threadIdx.x;
    s[threadIdx.x] = (i < Nn) ? g_cnti[i] : 0;
    __syncthreads();
    for (int o=128; o; o>>=1){
        if (threadIdx.x < o) s[threadIdx.x] += s[threadIdx.x+o];
        __syncthreads();
    }
    if (threadIdx.x == 0) g_bsum[blockIdx.x] = s[0];
}
__global__ void k_scan2(){
    __shared__ int s[256];
    int t = threadIdx.x;
    s[t] = (t < NBLK) ? g_bsum[t] : 0;
    __syncthreads();
    if (t == 0){
        int run = 0;
        for (int i=0;i<NBLK;i++){ int v=s[i]; s[i]=run; run+=v; }
    }
    __syncthreads();
    if (t < NBLK) g_boff[t] = s[t];
}
__global__ void k_scan3(){
    __shared__ int s[256];
    int t = threadIdx.x;
    int i = blockIdx.x*256 + t;
    int cnt = (i < Nn) ? g_cnti[i] : 0;
    s[t] = cnt;
    __syncthreads();
    for (int o=1; o<256; o<<=1){
        int v = (t >= o) ? s[t-o] : 0;
        __syncthreads();
        s[t] += v;
        __syncthreads();
    }
    int off = g_boff[blockIdx.x] + s[t] - cnt;
    if (i < Nn){
        g_off[i] = off;
        g_cursor[i] = off;
        g_cntf[i] = (float)cnt;
        if (i == Nn-1) g_off[Nn] = off + cnt;
    }
}
__global__ void k_bin(const int* __restrict__ ei){
    int e = blockIdx.x*blockDim.x + threadIdx.x;
    if (e >= Ee) return;
    int d = ei[Ee+e];
    int p = atomicAdd(&g_cursor[d], 1);
    g_eid[p]  = e;
    g_esrc[p] = ei[e];
}

// ---------- K1: edge LSTM — 2 edges/thread, 4 warps/block ----------
__global__ void __launch_bounds__(128) k_edge_lstm(
        const float* __restrict__ ea,
        const float* __restrict__ h0, const float* __restrict__ c0,
        const float* __restrict__ Wih, const float* __restrict__ Whh,
        const float* __restrict__ b, float* __restrict__ outp){
    extern __shared__ float dyn[];
    float* sQf  = dyn;
    float* sWih = dyn + 4096;
    float* sb   = dyn + 4352;
    for (int i=threadIdx.x; i<4096; i+=128){
        int r = i>>5, k = i&31;
        sQf[((k>>1)*64 + (r>>1))*4 + (r&1) + 2*(k&1)] = Whh[i];
    }
    for (int i=threadIdx.x; i<256; i+=128) sWih[i] = Wih[i];
    for (int i=threadIdx.x; i<128; i+=128) sb[i] = b[i];
    __syncthreads();

    int warp = threadIdx.x>>5, lane = threadIdx.x&31;
    int e0 = (blockIdx.x*4 + warp)*64;
    if (e0 >= Ee) return;
    float* mH = dyn + 4480 + warp*4096;
    float* mC = mH + 2048;

    {
        const float4* gh = (const float4*)(h0 + (size_t)e0*32);
        const float4* gc = (const float4*)(c0 + (size_t)e0*32);
        #pragma unroll
        for (int i=0;i<16;i++){
            int j = lane + 32*i;
            int e = j>>3, q = j&7;
            int slot = e*32 + ((q ^ (e&7))<<2);
            *(float4*)&mH[slot] = gh[j];
            *(float4*)&mC[slot] = gc[j];
        }
    }
    __syncwarp();

    float h[2][32];
    #pragma unroll
    for (int u=0;u<2;u++){
        int row = lane + 32*u;
        #pragma unroll
        for (int i=0;i<8;i++){
            float4 v = *(float4*)&mH[row*32 + ((i ^ (row&7))<<2)];
            h[u][4*i]=v.x; h[u][4*i+1]=v.y; h[u][4*i+2]=v.z; h[u][4*i+3]=v.w;
        }
    }
    float2 xv[2];
    xv[0] = ((const float2*)ea)[e0 + lane];
    xv[1] = ((const float2*)ea)[e0 + 32 + lane];
    const ulonglong2* sQ2 = (const ulonglong2*)sQf;

    #pragma unroll 1
    for (int j0=0;j0<32;j0+=4){
        u64 acc[2][4][2];
        #pragma unroll
        for (int u=0;u<2;u++)
            #pragma unroll
            for (int g=0; g<4; g++)
                #pragma unroll
                for (int p=0; p<2; p++){
                    int r0 = g*32 + j0 + 2*p;
                    float alo = sb[r0]   + xv[u].x*sWih[2*r0]   + xv[u].y*sWih[2*r0+1];
                    float ahi = sb[r0+1] + xv[u].x*sWih[2*r0+2] + xv[u].y*sWih[2*r0+3];
                    acc[u][g][p] = pk2(alo, ahi);
                }
        #pragma unroll
        for (int k2=0; k2<16; k2++){
            u64 x0lo = dup2(h[0][2*k2]), x0hi = dup2(h[0][2*k2+1]);
            u64 x1lo = dup2(h[1][2*k2]), x1hi = dup2(h[1][2*k2+1]);
            #pragma unroll
            for (int g=0; g<4; g++)
                #pragma unroll
                for (int p=0; p<2; p++){
                    ulonglong2 q = sQ2[k2*64 + g*16 + (j0>>1) + p];
                    fma2(acc[0][g][p], x0lo, q.x);
                    fma2(acc[0][g][p], x0hi, q.y);
                    fma2(acc[1][g][p], x1lo, q.x);
                    fma2(acc[1][g][p], x1hi, q.y);
                }
        }
        #pragma unroll
        for (int u=0;u<2;u++){
            float gi[4], gf[4], gg[4], go[4];
            #pragma unroll
            for (int p=0; p<2; p++){
                up2(acc[u][0][p], gi[2*p], gi[2*p+1]);
                up2(acc[u][1][p], gf[2*p], gf[2*p+1]);
                up2(acc[u][2][p], gg[2*p], gg[2*p+1]);
                up2(acc[u][3][p], go[2*p], go[2*p+1]);
            }
            int row = lane + 32*u;
            int slot = row*32 + (((j0>>2) ^ (row&7))<<2);
            float4 cv = *(float4*)&mC[slot];
            float cc[4] = {cv.x, cv.y, cv.z, cv.w};
            float h2a[4], c2a[4];
            #pragma unroll
            for (int t=0; t<4; t++){
                float c2 = fsig(gf[t])*cc[t] + fsig(gi[t])*tanha(gg[t]);
                float h2 = fsig(go[t])*tanha(c2);
                h2a[t]=h2; c2a[t]=c2;
            }
            *(float4*)&mH[slot] = make_float4(h2a[0],h2a[1],h2a[2],h2a[3]);
            *(float4*)&mC[slot] = make_float4(c2a[0],c2a[1],c2a[2],c2a[3]);
        }
    }
    __syncwarp();
    {
        float4* geh = (float4*)(outp + EH_OFF + (size_t)e0*32);
        float4* gec = (float4*)(outp + EC_OFF + (size_t)e0*32);
        #pragma unroll
        for (int i=0;i<16;i++){
            int j = lane + 32*i;
            int e = j>>3, q = j&7;
            int slot = e*32 + ((q ^ (e&7))<<2);
            geh[j] = *(float4*)&mH[slot];
            gec[j] = *(float4*)&mC[slot];
        }
    }
}

// ---------- K2: node LSTM ----------
__global__ void __launch_bounds__(128) k_node_lstm(
        const float* __restrict__ x, const float* __restrict__ h0,
        const float* __restrict__ c0, const float* __restrict__ Wih,
        const float* __restrict__ Whh, const float* __restrict__ b,
        float* __restrict__ outp){
    extern __shared__ float dyn[];
    float* sQf  = dyn;
    float* sWih = dyn + 16384;
    float* sb   = sWih + 1280;
    for (int i=threadIdx.x; i<16384; i+=128){
        int r = i>>6, k = i&63;
        sQf[((k>>1)*128 + (r>>1))*4 + (r&1) + 2*(k&1)] = Whh[i];
    }
    for (int i=threadIdx.x; i<1280; i+=128) sWih[i] = Wih[i];
    for (int i=threadIdx.x; i<256;  i+=128) sb[i] = b[i];
    __syncthreads();
    int node = blockIdx.x*128 + threadIdx.x;
    if (node >= Nn) return;

    float xr[5];
    #pragma unroll
    for (int k=0;k<5;k++) xr[k] = x[node*5+k];
    float h[64];
    {
        const float4* h0v = (const float4*)h0;
        #pragma unroll
        for (int i=0;i<16;i++){
            float4 v = h0v[node*16+i];
            h[4*i]=v.x; h[4*i+1]=v.y; h[4*i+2]=v.z; h[4*i+3]=v.w;
        }
    }
    const float4* c0v = (const float4*)c0;
    float4* outv = (float4*)outp;
    const ulonglong2* sQ2 = (const ulonglong2*)sQf;

    #pragma unroll 1
    for (int j0=0;j0<64;j0+=4){
        u64 acc[4][2];
        #pragma unroll
        for (int g=0; g<4; g++)
            #pragma unroll
            for (int p=0; p<2; p++){
                int r0 = g*64 + j0 + 2*p;
                float alo = sb[r0], ahi = sb[r0+1];
                #pragma unroll
                for (int k=0;k<5;k++){
                    alo += xr[k]*sWih[r0*5+k];
                    ahi += xr[k]*sWih[(r0+1)*5+k];
                }
                acc[g][p] = pk2(alo, ahi);
            }
        #pragma unroll
        for (int k2=0; k2<32; k2++){
            u64 xlo = dup2(h[2*k2]);
            u64 xhi = dup2(h[2*k2+1]);
            #pragma unroll
            for (int g=0; g<4; g++)
                #pragma unroll
                for (int p=0; p<2; p++){
                    ulonglong2 q = sQ2[k2*128 + g*32 + (j0>>1) + p];
                    fma2(acc[g][p], xlo, q.x);
                    fma2(acc[g][p], xhi, q.y);
                }
        }
        float gi[4], gf[4], gg[4], go[4];
        #pragma unroll
        for (int p=0; p<2; p++){
            up2(acc[0][p], gi[2*p], gi[2*p+1]);
            up2(acc[1][p], gf[2*p], gf[2*p+1]);
            up2(acc[2][p], gg[2*p], gg[2*p+1]);
            up2(acc[3][p], go[2*p], go[2*p+1]);
        }
        float4 cv = c0v[node*16 + (j0>>2)];
        float cc[4] = {cv.x, cv.y, cv.z, cv.w};
        float h2a[4], c2a[4];
        #pragma unroll
        for (int u=0; u<4; u++){
            float c2 = fsig(gf[u])*cc[u] + fsig(gi[u])*tanha(gg[u]);
            float h2 = fsig(go[u])*tanha(c2);
            h2a[u]=h2; c2a[u]=c2;
        }
        float4 h2v = make_float4(h2a[0],h2a[1],h2a[2],h2a[3]);
        outv[(NH_OFF + node*64 + j0)>>2] = h2v;
        outv[(NC_OFF + node*64 + j0)>>2] = make_float4(c2a[0],c2a[1],c2a[2],c2a[3]);
        ((float4*)g_xcat)[(node*96 + j0)>>2] = h2v;
    }
}

// ---------- K3: enc gather ----------
__global__ void __launch_bounds__(256) k_enc_gather(const float* __restrict__ outp){
    int warp = threadIdx.x>>5, lane = threadIdx.x&31;
    int n = blockIdx.x*8 + warp;
    if (n >= Nn) return;
    int beg = g_off[n], end = g_off[n+1];
    float acc = 0.f;
    for (int i=beg; i<end; i++){
        int e = g_eid[i];
        acc += outp[EH_OFF + e*32 + lane];
    }
    g_xcat[n*96 + 64 + lane] = __fdividef(acc, fmaxf(g_cntf[n], 1.f));
}

// ---------- K4: GAT projection + logits ----------
__global__ void __launch_bounds__(128) k_gat_proj(const float* __restrict__ W,
                                                  const float* __restrict__ att_s,
                                                  const float* __restrict__ att_d){
    extern __shared__ float dyn[];
    float* sQf = dyn;
    float* ss  = dyn + 24576;
    float* sd  = ss + 256;
    for (int i=threadIdx.x; i<24576; i+=128){
        int r = i/96, k = i - r*96;
        sQf[((k>>1)*128 + (r>>1))*4 + (r&1) + 2*(k&1)] = W[i];
    }
    for (int i=threadIdx.x; i<256; i+=128){ ss[i]=att_s[i]; sd[i]=att_d[i]; }
    __syncthreads();
    int n = blockIdx.x*128 + threadIdx.x;
    if (n >= Nn) return;

    float xc[96];
    {
        const float4* xv = (const float4*)(g_xcat + n*96);
        #pragma unroll
        for (int i=0;i<24;i++){
            float4 v = xv[i];
            xc[4*i]=v.x; xc[4*i+1]=v.y; xc[4*i+2]=v.z; xc[4*i+3]=v.w;
        }
    }
    const ulonglong2* sQ2 = (const ulonglong2*)sQf;
    float asa[4] = {0,0,0,0}, ada[4] = {0,0,0,0};

    #pragma unroll 1
    for (int rb=0; rb<16; rb++){
        u64 acc[8];
        #pragma unroll
        for (int p=0;p<8;p++) acc[p] = 0ull;
        #pragma unroll
        for (int k2=0; k2<48; k2++){
            u64 xlo = dup2(xc[2*k2]);
            u64 xhi = dup2(xc[2*k2+1]);
            #pragma unroll
            for (int p=0;p<8;p++){
                ulonglong2 q = sQ2[k2*128 + rb*8 + p];
                fma2(acc[p], xlo, q.x);
                fma2(acc[p], xhi, q.y);
            }
        }
        float v[16];
        #pragma unroll
        for (int p=0;p<8;p++) up2(acc[p], v[2*p], v[2*p+1]);
        int hd = rb>>2;
        #pragma unroll
        for (int u=0;u<16;u++){
            int r = rb*16 + u;
            asa[hd] += v[u]*ss[r];
            ada[hd] += v[u]*sd[r];
        }
        float4* xh4 = (float4*)(g_xh + (size_t)n*256 + rb*16);
        xh4[0] = make_float4(v[0],v[1],v[2],v[3]);
        xh4[1] = make_float4(v[4],v[5],v[6],v[7]);
        xh4[2] = make_float4(v[8],v[9],v[10],v[11]);
        xh4[3] = make_float4(v[12],v[13],v[14],v[15]);
    }
    *(float4*)&g_as[n*4] = make_float4(asa[0],asa[1],asa[2],asa[3]);
    *(float4*)&g_ad[n*4] = make_float4(ada[0],ada[1],ada[2],ada[3]);
}

// ---------- K5: GAT softmax+aggregate — batched-latency pass 2 ----------
__global__ void __launch_bounds__(256) k_gat_fused(const float* __restrict__ bias){
    __shared__ float sbias[64];
    if (threadIdx.x < 64) sbias[threadIdx.x] = bias[threadIdx.x];
    __syncthreads();
    int warp = threadIdx.x>>5, lane = threadIdx.x&31;
    int n = blockIdx.x*8 + warp;
    if (n >= Nn) return;
    float4 adv = *(const float4*)&g_ad[n*4];
    float4 asv = *(const float4*)&g_as[n*4];
    float m[4];
    m[0]=leaky(asv.x+adv.x); m[1]=leaky(asv.y+adv.y);
    m[2]=leaky(asv.z+adv.z); m[3]=leaky(asv.w+adv.w);
    float self[4] = {m[0],m[1],m[2],m[3]};
    int beg = g_off[n], end = g_off[n+1];
    // pass 1: strided max (lane-parallel)
    for (int i=beg+lane; i<end; i+=32){
        int s = g_esrc[i];
        float4 av = *(const float4*)&g_as[s*4];
        m[0]=fmaxf(m[0], leaky(av.x+adv.x));
        m[1]=fmaxf(m[1], leaky(av.y+adv.y));
        m[2]=fmaxf(m[2], leaky(av.z+adv.z));
        m[3]=fmaxf(m[3], leaky(av.w+adv.w));
    }
    #pragma unroll
    for (int off=16; off; off>>=1)
        #pragma unroll
        for (int h=0;h<4;h++) m[h] = fmaxf(m[h], __shfl_xor_sync(0xffffffff, m[h], off));
    // init with self-loop
    float den[4], accA[4], accB[4];
    const float* xn = &g_xh[(size_t)n*256];
    #pragma unroll
    for (int h=0;h<4;h++){
        float w = __expf(self[h] - m[h]);
        den[h] = w;
        accA[h] = w * xn[h*64 + lane];
        accB[h] = w * xn[h*64 + 32 + lane];
    }
    // pass 2: chunk of 32 edges — weights computed lane-parallel, xh loads batched 4-deep
    for (int i0=beg; i0<end; i0+=32){
        int cnt = min(32, end - i0);
        int sv = 0;
        float w4[4] = {0.f,0.f,0.f,0.f};
        if (lane < cnt){
            sv = g_esrc[i0 + lane];
            float4 av = *(const float4*)&g_as[sv*4];
            w4[0] = __expf(leaky(av.x+adv.x) - m[0]);
            w4[1] = __expf(leaky(av.y+adv.y) - m[1]);
            w4[2] = __expf(leaky(av.z+adv.z) - m[2]);
            w4[3] = __expf(leaky(av.w+adv.w) - m[3]);
        }
        for (int j=0; j<cnt; j+=4){
            int jn = min(4, cnt - j);
            int ss[4];
            float ww[4][4];
            #pragma unroll
            for (int q=0;q<4;q++){
                int idx = (q < jn) ? (j+q) : j;
                ss[q] = __shfl_sync(0xffffffff, sv, idx);
                ww[q][0] = __shfl_sync(0xffffffff, w4[0], idx);
                ww[q][1] = __shfl_sync(0xffffffff, w4[1], idx);
                ww[q][2] = __shfl_sync(0xffffffff, w4[2], idx);
                ww[q][3] = __shfl_sync(0xffffffff, w4[3], idx);
            }
            float bA[4][4], bB[4][4];
            #pragma unroll
            for (int q=0;q<4;q++){
                const float* xs = &g_xh[(size_t)ss[q]*256];
                #pragma unroll
                for (int h=0;h<4;h++){
                    bA[q][h] = xs[h*64 + lane];
                    bB[q][h] = xs[h*64 + 32 + lane];
                }
            }
            #pragma unroll
            for (int q=0;q<4;q++){
                if (q < jn){
                    #pragma unroll
                    for (int h=0;h<4;h++){
                        den[h] += ww[q][h];
                        accA[h] = fmaf(ww[q][h], bA[q][h], accA[h]);
                        accB[h] = fmaf(ww[q][h], bB[q][h], accB[h]);
                    }
                }
            }
        }
    }
    // den is lane-redundant except each lane added shfl'd copies identically; but den
    // accumulated w per-lane duplicates across q-guard identically in all lanes -> uniform.
    // NOTE: den[h] currently counted each edge once per lane (uniform adds) == correct scalar.
    float rA = 0.f, rB = 0.f;
    #pragma unroll
    for (int h=0;h<4;h++){
        float inv = __fdividef(1.f, den[h]);
        rA += accA[h]*inv;
        rB += accB[h]*inv;
    }
    g_xgat[n*64 + lane]      = rA*0.25f + sbias[lane];
    g_xgat[n*64 + 32 + lane] = rB*0.25f + sbias[32 + lane];
}

// ---------- K6: P/Q ----------
__global__ void __launch_bounds__(256) k_pq(const float* __restrict__ W1, const float* __restrict__ b1){
    __shared__ float sQf[8192];
    __shared__ float sb1[64];
    for (int i=threadIdx.x; i<8192; i+=256){
        int R = i>>6, k = i&63;
        float v = (R < 64) ? W1[R*130 + k] : W1[(R-64)*130 + 64 + k];
        sQf[((k>>1)*64 + (R>>1))*4 + (R&1) + 2*(k&1)] = v;
    }
    for (int i=threadIdx.x; i<64; i+=256) sb1[i]=b1[i];
    __syncthreads();
    int n = blockIdx.x*256 + threadIdx.x;
    if (n >= Nn) return;

    float xg[64];
    {
        const float4* xv = (const float4*)(g_xgat + n*64);
        #pragma unroll
        for (int i=0;i<16;i++){
            float4 v = xv[i];
            xg[4*i]=v.x; xg[4*i+1]=v.y; xg[4*i+2]=v.z; xg[4*i+3]=v.w;
        }
    }
    const ulonglong2* sQ2 = (const ulonglong2*)sQf;
    #pragma unroll 1
    for (int rb=0; rb<8; rb++){
        u64 acc[8];
        #pragma unroll
        for (int p=0;p<8;p++){
            int r = rb*16 + 2*p;
            acc[p] = (rb < 4) ? pk2(sb1[r], sb1[r+1]) : 0ull;
        }
        #pragma unroll
        for (int k2=0; k2<32; k2++){
            u64 xlo = dup2(xg[2*k2]);
            u64 xhi = dup2(xg[2*k2+1]);
            #pragma unroll
            for (int p=0;p<8;p++){
                ulonglong2 q = sQ2[k2*64 + rb*8 + p];
                fma2(acc[p], xlo, q.x);
                fma2(acc[p], xhi, q.y);
            }
        }
        float v[16];
        #pragma unroll
        for (int p=0;p<8;p++) up2(acc[p], v[2*p], v[2*p+1]);
        float* dst = (rb < 4) ? (g_P + n*64 + rb*16) : (g_Q + n*64 + (rb-4)*16);
        float4* d4 = (float4*)dst;
        d4[0] = make_float4(v[0],v[1],v[2],v[3]);
        d4[1] = make_float4(v[4],v[5],v[6],v[7]);
        d4[2] = make_float4(v[8],v[9],v[10],v[11]);
        d4[3] = make_float4(v[12],v[13],v[14],v[15]);
    }
}

// ---------- K7: edge MLP -> e_lat (streaming) ----------
__global__ void __launch_bounds__(256) k_edge_mlp(
        const int* __restrict__ ei, const float* __restrict__ ea,
        const float* __restrict__ W1, const float* __restrict__ W2,
        const float* __restrict__ b2){
    __shared__ float sW2dq[32*33*4];
    __shared__ float sw128[64], sw129[64], sb2[32];
    extern __shared__ float sHf[];
    for (int i=threadIdx.x; i<2048; i+=256){
        int l = i>>6, j = i&63;
        float v = W2[l*64+j];
        int base = (l*33 + (j>>1))*4 + 2*(j&1);
        sW2dq[base] = v; sW2dq[base+1] = v;
    }
    for (int i=threadIdx.x; i<64; i+=256){
        sw128[i]=W1[i*130+128]; sw129[i]=W1[i*130+129];
    }
    if (threadIdx.x < 32) sb2[threadIdx.x]=b2[threadIdx.x];
    __syncthreads();
    int warp = threadIdx.x>>5, lane = threadIdx.x&31;
    int base_e = (blockIdx.x*8 + warp)*16;
    if (base_e >= Ee) return;

    float* myH = sHf + warp*1024;
    for (int el=0; el<16; el++){
        int e = base_e + el;
        int s = ei[e], d = ei[Ee+e];
        float2 ev = ((const float2*)ea)[e];
        float h0 = fmaxf(g_P[s*64+lane]    + g_Q[d*64+lane]    + ev.x*sw128[lane]    + ev.y*sw129[lane],    0.f);
        float h1 = fmaxf(g_P[s*64+32+lane] + g_Q[d*64+32+lane] + ev.x*sw128[32+lane] + ev.y*sw129[32+lane], 0.f);
        int ep = el>>1, c = el&1;
        int j = lane;
        myH[(ep*32 + (j>>1))*4 + 2*(j&1) + c] = h0;
        j = lane + 32;
        myH[(ep*32 + (j>>1))*4 + 2*(j&1) + c] = h1;
    }
    __syncwarp();
    u64 acc[8];
    #pragma unroll
    for (int ep=0;ep<8;ep++) acc[ep] = dup2(sb2[lane]);
    const ulonglong2* sW2q = (const ulonglong2*)sW2dq;
    const ulonglong2* sH2 = (const ulonglong2*)myH;
    #pragma unroll 4
    for (int j2=0; j2<32; j2++){
        ulonglong2 qw = sW2q[lane*33 + j2];
        #pragma unroll
        for (int ep=0;ep<8;ep++){
            ulonglong2 xq = sH2[ep*32 + j2];
            fma2(acc[ep], xq.x, qw.x);
            fma2(acc[ep], xq.y, qw.y);
        }
    }
    #pragma unroll
    for (int ep=0;ep<8;ep++){
        float o0, o1;
        up2(acc[ep], o0, o1);
        g_elat[(base_e + 2*ep)*32 + lane]   = o0;
        g_elat[(base_e + 2*ep+1)*32 + lane] = o1;
    }
}

// ---------- K8: agg gather ----------
__global__ void __launch_bounds__(256) k_agg_gather(){
    int warp = threadIdx.x>>5, lane = threadIdx.x&31;
    int n = blockIdx.x*8 + warp;
    if (n >= Nn) return;
    int beg = g_off[n], end = g_off[n+1];
    float acc = 0.f;
    for (int i=beg; i<end; i++){
        int e = g_eid[i];
        acc += g_elat[e*32 + lane];
    }
    g_agg[n*32 + lane] = __fdividef(acc, fmaxf(g_cntf[n], 1.f));
}

// ---------- K9: node MLP ----------
__global__ void __launch_bounds__(128) k_node_mlp(
        const float* __restrict__ W1, const float* __restrict__ b1,
        const float* __restrict__ W2, const float* __restrict__ b2,
        float* __restrict__ outp){
    __shared__ float sQf[6144];
    __shared__ float sW2[256];
    __shared__ float sb1[64];
    for (int i=threadIdx.x; i<6144; i+=128){
        int r = i/96, k = i - r*96;
        sQf[((k>>1)*32 + (r>>1))*4 + (r&1) + 2*(k&1)] = W1[i];
    }
    for (int i=threadIdx.x; i<256; i+=128) sW2[i]=W2[i];
    for (int i=threadIdx.x; i<64;  i+=128) sb1[i]=b1[i];
    __syncthreads();
    int n = blockIdx.x*128 + threadIdx.x;
    if (n >= Nn) return;

    float xc[96];
    {
        const float4* xv = (const float4*)(g_xgat + n*64);
        #pragma unroll
        for (int i=0;i<16;i++){
            float4 v = xv[i];
            xc[4*i]=v.x; xc[4*i+1]=v.y; xc[4*i+2]=v.z; xc[4*i+3]=v.w;
        }
        const float4* av = (const float4*)(g_agg + n*32);
        #pragma unroll
        for (int i=0;i<8;i++){
            float4 v = av[i];
            xc[64+4*i]=v.x; xc[64+4*i+1]=v.y; xc[64+4*i+2]=v.z; xc[64+4*i+3]=v.w;
        }
    }
    const ulonglong2* sQ2 = (const ulonglong2*)sQf;
    float p[4] = {0,0,0,0};
    #pragma unroll 1
    for (int rb=0; rb<4; rb++){
        u64 acc[8];
        #pragma unroll
        for (int q=0;q<8;q++){
            int r = rb*16 + 2*q;
            acc[q] = pk2(sb1[r], sb1[r+1]);
        }
        #pragma unroll
        for (int k2=0; k2<48; k2++){
            u64 xlo = dup2(xc[2*k2]);
            u64 xhi = dup2(xc[2*k2+1]);
            #pragma unroll
            for (int q=0;q<8;q++){
                ulonglong2 w = sQ2[k2*32 + rb*8 + q];
                fma2(acc[q], xlo, w.x);
                fma2(acc[q], xhi, w.y);
            }
        }
        #pragma unroll
        for (int q=0;q<8;q++){
            float vlo, vhi;
            up2(acc[q], vlo, vhi);
            int r = rb*16 + 2*q;
            vlo = fmaxf(vlo, 0.f); vhi = fmaxf(vhi, 0.f);
            #pragma unroll
            for (int o=0;o<4;o++)
                p[o] += vlo*sW2[o*64 + r] + vhi*sW2[o*64 + r + 1];
        }
    }
    *(float4*)&outp[OUT_OFF + n*4] = make_float4(p[0]+b2[0], p[1]+b2[1], p[2]+b2[2], p[3]+b2[3]);
}

extern "C" void kernel_launch(void* const* d_in, const int* in_sizes, int n_in,
                              void* d_out, int out_size){
    (void)in_sizes; (void)n_in; (void)out_size;
    const float* x    = (const float*)d_in[0];
    const int*   ei   = (const int*)  d_in[1];
    const float* ea   = (const float*)d_in[2];
    const float* hnh  = (const float*)d_in[3];
    const float* hnc  = (const float*)d_in[4];
    const float* heh  = (const float*)d_in[5];
    const float* hec  = (const float*)d_in[6];
    const float* nWih = (const float*)d_in[7];
    const float* nWhh = (const float*)d_in[8];
    const float* nb   = (const float*)d_in[9];
    const float* eWih = (const float*)d_in[10];
    const float* eWhh = (const float*)d_in[11];
    const float* eb   = (const float*)d_in[12];
    const float* gatW = (const float*)d_in[13];
    const float* attS = (const float*)d_in[14];
    const float* attD = (const float*)d_in[15];
    const float* gatB = (const float*)d_in[16];
    const float* emW1 = (const float*)d_in[17];
    const float* emb1 = (const float*)d_in[18];
    const float* emW2 = (const float*)d_in[19];
    const float* emb2 = (const float*)d_in[20];
    const float* nmW1 = (const float*)d_in[21];
    const float* nmb1 = (const float*)d_in[22];
    const float* nmW2 = (const float*)d_in[23];
    const float* nmb2 = (const float*)d_in[24];
    float* out = (float*)d_out;

    static const int elstm_smem = (4480 + 4*4096)*4;             // 83456
    static const int nlstm_smem = (16384 + 1280 + 256)*4;        // 71680
    static const int gproj_smem = (24576 + 512)*4;               // 100352
    static const int emlp_smem  = 8192*4;                        // 32768

    static bool init_done = false;
    static cudaStream_t sB;
    static cudaEvent_t evFork, evJoin;
    if (!init_done){
        cudaFuncSetAttribute(k_edge_lstm, cudaFuncAttributeMaxDynamicSharedMemorySize, elstm_smem);
        cudaFuncSetAttribute(k_node_lstm, cudaFuncAttributeMaxDynamicSharedMemorySize, nlstm_smem);
        cudaFuncSetAttribute(k_gat_proj,  cudaFuncAttributeMaxDynamicSharedMemorySize, gproj_smem);
        cudaFuncSetAttribute(k_edge_mlp,  cudaFuncAttributeMaxDynamicSharedMemorySize, emlp_smem);
        cudaStreamCreateWithFlags(&sB, cudaStreamNonBlocking);
        cudaEventCreateWithFlags(&evFork, cudaEventDisableTiming);
        cudaEventCreateWithFlags(&evJoin, cudaEventDisableTiming);
        init_done = true;
    }

    // fork side stream B off the origin stream
    cudaEventRecord(evFork, 0);
    cudaStreamWaitEvent(sB, evFork, 0);

    // stream B: CSR build + node LSTM (independent of edge LSTM)
    k_zero_cnt<<<NBLK, 256, 0, sB>>>();
    k_count<<<(Ee+255)/256, 256, 0, sB>>>(ei);
    k_scan1<<<NBLK, 256, 0, sB>>>();

    // origin stream: edge LSTM (ncu capture slot)
    k_edge_lstm<<<(Ee/64 + 3)/4, 128, elstm_smem>>>(ea, heh, hec, eWih, eWhh, eb, out);

    k_scan2<<<1, 256, 0, sB>>>();
    k_scan3<<<NBLK, 256, 0, sB>>>();
    k_bin<<<(Ee+255)/256, 256, 0, sB>>>(ei);
    k_node_lstm<<<(Nn+127)/128, 128, nlstm_smem, sB>>>(x, hnh, hnc, nWih, nWhh, nb, out);

    // join
    cudaEventRecord(evJoin, sB);
    cudaStreamWaitEvent(0, evJoin, 0);

    // serial tail on origin stream
    k_enc_gather<<<(Nn+7)/8, 256>>>(out);
    k_gat_proj<<<(Nn+127)/128, 128, gproj_smem>>>(gatW, attS, attD);
    k_gat_fused<<<(Nn+7)/8, 256>>>(gatB);
    k_pq<<<(Nn+255)/256, 256>>>(emW1, emb1);
    k_edge_mlp<<<(Ee+127)/128, 256, emlp_smem>>>(ei, ea, emW1, emW2, emb2);
    k_agg_gather<<<(Nn+7)/8, 256>>>();
    k_node_mlp<<<(Nn+127)/128, 128>>>(nmW1, nmb1, nmW2, nmb2, out);
}

// round 14
// speedup vs baseline: 1.0063x; 1.0063x over previous
#include <cuda_runtime.h>
#include <math.h>

#define Nn 50000
#define Ee 400000
#define NBLK 196   // ceil(Nn/256)

// output packing: out[N*4], nh[N*64], nc[N*64], eh[E*32], ec[E*32]
#define OUT_OFF 0
#define NH_OFF  (Nn*4)
#define NC_OFF  (NH_OFF + Nn*64)
#define EH_OFF  (NC_OFF + Nn*64)
#define EC_OFF  (EH_OFF + Ee*32)

// ---------------- scratch ----------------
__device__ int   g_cnti[Nn];
__device__ int   g_bsum[256];
__device__ int   g_boff[256];
__device__ int   g_off[Nn+1];
__device__ int   g_cursor[Nn];
__device__ int   g_eid[Ee];
__device__ int   g_esrc[Ee];
__device__ float g_cntf[Nn];
__device__ float g_xcat[Nn*96];
__device__ float g_xh[Nn*256];
__device__ float g_as[Nn*4];
__device__ float g_ad[Nn*4];
__device__ float g_xgat[Nn*64];
__device__ float g_P[Nn*64];
__device__ float g_Q[Nn*64];
__device__ float g_elat[Ee*32];
__device__ float g_agg[Nn*32];

typedef unsigned long long u64;
__device__ __forceinline__ u64 pk2(float lo, float hi){ u64 r; asm("mov.b64 %0, {%1,%2};" : "=l"(r) : "f"(lo), "f"(hi)); return r; }
__device__ __forceinline__ u64 dup2(float v){ return pk2(v,v); }
__device__ __forceinline__ void fma2(u64 &acc, u64 a, u64 b){ asm("fma.rn.f32x2 %0, %1, %2, %0;" : "+l"(acc) : "l"(a), "l"(b)); }
__device__ __forceinline__ void up2(u64 v, float &lo, float &hi){ asm("mov.b64 {%0,%1}, %2;" : "=f"(lo), "=f"(hi) : "l"(v)); }

__device__ __forceinline__ float tanha(float x){ float r; asm("tanh.approx.f32 %0, %1;" : "=f"(r) : "f"(x)); return r; }
__device__ __forceinline__ float fsig(float x){ return fmaf(0.5f, tanha(0.5f*x), 0.5f); }
__device__ __forceinline__ float leaky(float x){ return x > 0.f ? x : 0.2f*x; }

// ================= CSR build =================
__global__ void k_zero_cnt(){
    int t = blockIdx.x*blockDim.x + threadIdx.x;
    if (t < Nn) g_cnti[t] = 0;
}
__global__ void k_count(const int* __restrict__ ei){
    int e = blockIdx.x*blockDim.x + threadIdx.x;
    if (e < Ee) atomicAdd(&g_cnti[ei[Ee+e]], 1);
}
__global__ void k_scan1(){
    __shared__ int s[256];
    int i = blockIdx.x*256 + threadIdx.x;
    s[threadIdx.x] = (i < Nn) ? g_cnti[i] : 0;
    __syncthreads();
    for (int o=128; o; o>>=1){
        if (threadIdx.x < o) s[threadIdx.x] += s[threadIdx.x+o];
        __syncthreads();
    }
    if (threadIdx.x == 0) g_bsum[blockIdx.x] = s[0];
}
__global__ void k_scan2(){
    __shared__ int s[256];
    int t = threadIdx.x;
    s[t] = (t < NBLK) ? g_bsum[t] : 0;
    __syncthreads();
    if (t == 0){
        int run = 0;
        for (int i=0;i<NBLK;i++){ int v=s[i]; s[i]=run; run+=v; }
    }
    __syncthreads();
    if (t < NBLK) g_boff[t] = s[t];
}
__global__ void k_scan3(){
    __shared__ int s[256];
    int t = threadIdx.x;
    int i = blockIdx.x*256 + t;
    int cnt = (i < Nn) ? g_cnti[i] : 0;
    s[t] = cnt;
    __syncthreads();
    for (int o=1; o<256; o<<=1){
        int v = (t >= o) ? s[t-o] : 0;
        __syncthreads();
        s[t] += v;
        __syncthreads();
    }
    int off = g_boff[blockIdx.x] + s[t] - cnt;
    if (i < Nn){
        g_off[i] = off;
        g_cursor[i] = off;
        g_cntf[i] = (float)cnt;
        if (i == Nn-1) g_off[Nn] = off + cnt;
    }
}
__global__ void k_bin(const int* __restrict__ ei){
    int e = blockIdx.x*blockDim.x + threadIdx.x;
    if (e >= Ee) return;
    int d = ei[Ee+e];
    int p = atomicAdd(&g_cursor[d], 1);
    g_eid[p]  = e;
    g_esrc[p] = ei[e];
}

// ---------- K1: edge LSTM — 2 edges/thread, 4 warps/block ----------
__global__ void __launch_bounds__(128) k_edge_lstm(
        const float* __restrict__ ea,
        const float* __restrict__ h0, const float* __restrict__ c0,
        const float* __restrict__ Wih, const float* __restrict__ Whh,
        const float* __restrict__ b, float* __restrict__ outp){
    extern __shared__ float dyn[];
    float* sQf  = dyn;
    float* sWih = dyn + 4096;
    float* sb   = dyn + 4352;
    for (int i=threadIdx.x; i<4096; i+=128){
        int r = i>>5, k = i&31;
        sQf[((k>>1)*64 + (r>>1))*4 + (r&1) + 2*(k&1)] = Whh[i];
    }
    for (int i=threadIdx.x; i<256; i+=128) sWih[i] = Wih[i];
    for (int i=threadIdx.x; i<128; i+=128) sb[i] = b[i];
    __syncthreads();

    int warp = threadIdx.x>>5, lane = threadIdx.x&31;
    int e0 = (blockIdx.x*4 + warp)*64;
    if (e0 >= Ee) return;
    float* mH = dyn + 4480 + warp*4096;
    float* mC = mH + 2048;

    {
        const float4* gh = (const float4*)(h0 + (size_t)e0*32);
        const float4* gc = (const float4*)(c0 + (size_t)e0*32);
        #pragma unroll
        for (int i=0;i<16;i++){
            int j = lane + 32*i;
            int e = j>>3, q = j&7;
            int slot = e*32 + ((q ^ (e&7))<<2);
            *(float4*)&mH[slot] = gh[j];
            *(float4*)&mC[slot] = gc[j];
        }
    }
    __syncwarp();

    float h[2][32];
    #pragma unroll
    for (int u=0;u<2;u++){
        int row = lane + 32*u;
        #pragma unroll
        for (int i=0;i<8;i++){
            float4 v = *(float4*)&mH[row*32 + ((i ^ (row&7))<<2)];
            h[u][4*i]=v.x; h[u][4*i+1]=v.y; h[u][4*i+2]=v.z; h[u][4*i+3]=v.w;
        }
    }
    float2 xv[2];
    xv[0] = ((const float2*)ea)[e0 + lane];
    xv[1] = ((const float2*)ea)[e0 + 32 + lane];
    const ulonglong2* sQ2 = (const ulonglong2*)sQf;

    #pragma unroll 1
    for (int j0=0;j0<32;j0+=4){
        u64 acc[2][4][2];
        #pragma unroll
        for (int u=0;u<2;u++)
            #pragma unroll
            for (int g=0; g<4; g++)
                #pragma unroll
                for (int p=0; p<2; p++){
                    int r0 = g*32 + j0 + 2*p;
                    float alo = sb[r0]   + xv[u].x*sWih[2*r0]   + xv[u].y*sWih[2*r0+1];
                    float ahi = sb[r0+1] + xv[u].x*sWih[2*r0+2] + xv[u].y*sWih[2*r0+3];
                    acc[u][g][p] = pk2(alo, ahi);
                }
        #pragma unroll
        for (int k2=0; k2<16; k2++){
            u64 x0lo = dup2(h[0][2*k2]), x0hi = dup2(h[0][2*k2+1]);
            u64 x1lo = dup2(h[1][2*k2]), x1hi = dup2(h[1][2*k2+1]);
            #pragma unroll
            for (int g=0; g<4; g++)
                #pragma unroll
                for (int p=0; p<2; p++){
                    ulonglong2 q = sQ2[k2*64 + g*16 + (j0>>1) + p];
                    fma2(acc[0][g][p], x0lo, q.x);
                    fma2(acc[0][g][p], x0hi, q.y);
                    fma2(acc[1][g][p], x1lo, q.x);
                    fma2(acc[1][g][p], x1hi, q.y);
                }
        }
        #pragma unroll
        for (int u=0;u<2;u++){
            float gi[4], gf[4], gg[4], go[4];
            #pragma unroll
            for (int p=0; p<2; p++){
                up2(acc[u][0][p], gi[2*p], gi[2*p+1]);
                up2(acc[u][1][p], gf[2*p], gf[2*p+1]);
                up2(acc[u][2][p], gg[2*p], gg[2*p+1]);
                up2(acc[u][3][p], go[2*p], go[2*p+1]);
            }
            int row = lane + 32*u;
            int slot = row*32 + (((j0>>2) ^ (row&7))<<2);
            float4 cv = *(float4*)&mC[slot];
            float cc[4] = {cv.x, cv.y, cv.z, cv.w};
            float h2a[4], c2a[4];
            #pragma unroll
            for (int t=0; t<4; t++){
                float c2 = fsig(gf[t])*cc[t] + fsig(gi[t])*tanha(gg[t]);
                float h2 = fsig(go[t])*tanha(c2);
                h2a[t]=h2; c2a[t]=c2;
            }
            *(float4*)&mH[slot] = make_float4(h2a[0],h2a[1],h2a[2],h2a[3]);
            *(float4*)&mC[slot] = make_float4(c2a[0],c2a[1],c2a[2],c2a[3]);
        }
    }
    __syncwarp();
    {
        float4* geh = (float4*)(outp + EH_OFF + (size_t)e0*32);
        float4* gec = (float4*)(outp + EC_OFF + (size_t)e0*32);
        #pragma unroll
        for (int i=0;i<16;i++){
            int j = lane + 32*i;
            int e = j>>3, q = j&7;
            int slot = e*32 + ((q ^ (e&7))<<2);
            geh[j] = *(float4*)&mH[slot];
            gec[j] = *(float4*)&mC[slot];
        }
    }
}

// ---------- K2: node LSTM ----------
__global__ void __launch_bounds__(128) k_node_lstm(
        const float* __restrict__ x, const float* __restrict__ h0,
        const float* __restrict__ c0, const float* __restrict__ Wih,
        const float* __restrict__ Whh, const float* __restrict__ b,
        float* __restrict__ outp){
    extern __shared__ float dyn[];
    float* sQf  = dyn;
    float* sWih = dyn + 16384;
    float* sb   = sWih + 1280;
    for (int i=threadIdx.x; i<16384; i+=128){
        int r = i>>6, k = i&63;
        sQf[((k>>1)*128 + (r>>1))*4 + (r&1) + 2*(k&1)] = Whh[i];
    }
    for (int i=threadIdx.x; i<1280; i+=128) sWih[i] = Wih[i];
    for (int i=threadIdx.x; i<256;  i+=128) sb[i] = b[i];
    __syncthreads();
    int node = blockIdx.x*128 + threadIdx.x;
    if (node >= Nn) return;

    float xr[5];
    #pragma unroll
    for (int k=0;k<5;k++) xr[k] = x[node*5+k];
    float h[64];
    {
        const float4* h0v = (const float4*)h0;
        #pragma unroll
        for (int i=0;i<16;i++){
            float4 v = h0v[node*16+i];
            h[4*i]=v.x; h[4*i+1]=v.y; h[4*i+2]=v.z; h[4*i+3]=v.w;
        }
    }
    const float4* c0v = (const float4*)c0;
    float4* outv = (float4*)outp;
    const ulonglong2* sQ2 = (const ulonglong2*)sQf;

    #pragma unroll 1
    for (int j0=0;j0<64;j0+=4){
        u64 acc[4][2];
        #pragma unroll
        for (int g=0; g<4; g++)
            #pragma unroll
            for (int p=0; p<2; p++){
                int r0 = g*64 + j0 + 2*p;
                float alo = sb[r0], ahi = sb[r0+1];
                #pragma unroll
                for (int k=0;k<5;k++){
                    alo += xr[k]*sWih[r0*5+k];
                    ahi += xr[k]*sWih[(r0+1)*5+k];
                }
                acc[g][p] = pk2(alo, ahi);
            }
        #pragma unroll
        for (int k2=0; k2<32; k2++){
            u64 xlo = dup2(h[2*k2]);
            u64 xhi = dup2(h[2*k2+1]);
            #pragma unroll
            for (int g=0; g<4; g++)
                #pragma unroll
                for (int p=0; p<2; p++){
                    ulonglong2 q = sQ2[k2*128 + g*32 + (j0>>1) + p];
                    fma2(acc[g][p], xlo, q.x);
                    fma2(acc[g][p], xhi, q.y);
                }
        }
        float gi[4], gf[4], gg[4], go[4];
        #pragma unroll
        for (int p=0; p<2; p++){
            up2(acc[0][p], gi[2*p], gi[2*p+1]);
            up2(acc[1][p], gf[2*p], gf[2*p+1]);
            up2(acc[2][p], gg[2*p], gg[2*p+1]);
            up2(acc[3][p], go[2*p], go[2*p+1]);
        }
        float4 cv = c0v[node*16 + (j0>>2)];
        float cc[4] = {cv.x, cv.y, cv.z, cv.w};
        float h2a[4], c2a[4];
        #pragma unroll
        for (int u=0; u<4; u++){
            float c2 = fsig(gf[u])*cc[u] + fsig(gi[u])*tanha(gg[u]);
            float h2 = fsig(go[u])*tanha(c2);
            h2a[u]=h2; c2a[u]=c2;
        }
        float4 h2v = make_float4(h2a[0],h2a[1],h2a[2],h2a[3]);
        outv[(NH_OFF + node*64 + j0)>>2] = h2v;
        outv[(NC_OFF + node*64 + j0)>>2] = make_float4(c2a[0],c2a[1],c2a[2],c2a[3]);
        ((float4*)g_xcat)[(node*96 + j0)>>2] = h2v;
    }
}

// ---------- K3: enc gather (unroll-2 dual accumulators) ----------
__global__ void __launch_bounds__(256) k_enc_gather(const float* __restrict__ outp){
    int warp = threadIdx.x>>5, lane = threadIdx.x&31;
    int n = blockIdx.x*8 + warp;
    if (n >= Nn) return;
    int beg = g_off[n], end = g_off[n+1];
    float acc0 = 0.f, acc1 = 0.f;
    int i = beg;
    for (; i+1 < end; i += 2){
        int e0 = g_eid[i], e1 = g_eid[i+1];
        acc0 += outp[EH_OFF + e0*32 + lane];
        acc1 += outp[EH_OFF + e1*32 + lane];
    }
    if (i < end) acc0 += outp[EH_OFF + g_eid[i]*32 + lane];
    g_xcat[n*96 + 64 + lane] = __fdividef(acc0 + acc1, fmaxf(g_cntf[n], 1.f));
}

// ---------- K4: GAT projection + logits ----------
__global__ void __launch_bounds__(128) k_gat_proj(const float* __restrict__ W,
                                                  const float* __restrict__ att_s,
                                                  const float* __restrict__ att_d){
    extern __shared__ float dyn[];
    float* sQf = dyn;
    float* ss  = dyn + 24576;
    float* sd  = ss + 256;
    for (int i=threadIdx.x; i<24576; i+=128){
        int r = i/96, k = i - r*96;
        sQf[((k>>1)*128 + (r>>1))*4 + (r&1) + 2*(k&1)] = W[i];
    }
    for (int i=threadIdx.x; i<256; i+=128){ ss[i]=att_s[i]; sd[i]=att_d[i]; }
    __syncthreads();
    int n = blockIdx.x*128 + threadIdx.x;
    if (n >= Nn) return;

    float xc[96];
    {
        const float4* xv = (const float4*)(g_xcat + n*96);
        #pragma unroll
        for (int i=0;i<24;i++){
            float4 v = xv[i];
            xc[4*i]=v.x; xc[4*i+1]=v.y; xc[4*i+2]=v.z; xc[4*i+3]=v.w;
        }
    }
    const ulonglong2* sQ2 = (const ulonglong2*)sQf;
    float asa[4] = {0,0,0,0}, ada[4] = {0,0,0,0};

    #pragma unroll 1
    for (int rb=0; rb<16; rb++){
        u64 acc[8];
        #pragma unroll
        for (int p=0;p<8;p++) acc[p] = 0ull;
        #pragma unroll
        for (int k2=0; k2<48; k2++){
            u64 xlo = dup2(xc[2*k2]);
            u64 xhi = dup2(xc[2*k2+1]);
            #pragma unroll
            for (int p=0;p<8;p++){
                ulonglong2 q = sQ2[k2*128 + rb*8 + p];
                fma2(acc[p], xlo, q.x);
                fma2(acc[p], xhi, q.y);
            }
        }
        float v[16];
        #pragma unroll
        for (int p=0;p<8;p++) up2(acc[p], v[2*p], v[2*p+1]);
        int hd = rb>>2;
        #pragma unroll
        for (int u=0;u<16;u++){
            int r = rb*16 + u;
            asa[hd] += v[u]*ss[r];
            ada[hd] += v[u]*sd[r];
        }
        float4* xh4 = (float4*)(g_xh + (size_t)n*256 + rb*16);
        xh4[0] = make_float4(v[0],v[1],v[2],v[3]);
        xh4[1] = make_float4(v[4],v[5],v[6],v[7]);
        xh4[2] = make_float4(v[8],v[9],v[10],v[11]);
        xh4[3] = make_float4(v[12],v[13],v[14],v[15]);
    }
    *(float4*)&g_as[n*4] = make_float4(asa[0],asa[1],asa[2],asa[3]);
    *(float4*)&g_ad[n*4] = make_float4(ada[0],ada[1],ada[2],ada[3]);
}

// ---------- K5: GAT softmax+aggregate (two-pass, unroll-2 pass 2) ----------
__global__ void __launch_bounds__(256) k_gat_fused(const float* __restrict__ bias){
    __shared__ float sbias[64];
    if (threadIdx.x < 64) sbias[threadIdx.x] = bias[threadIdx.x];
    __syncthreads();
    int warp = threadIdx.x>>5, lane = threadIdx.x&31;
    int n = blockIdx.x*8 + warp;
    if (n >= Nn) return;
    float4 adv = *(const float4*)&g_ad[n*4];
    float4 asv = *(const float4*)&g_as[n*4];
    float m[4];
    m[0]=leaky(asv.x+adv.x); m[1]=leaky(asv.y+adv.y);
    m[2]=leaky(asv.z+adv.z); m[3]=leaky(asv.w+adv.w);
    float self[4] = {m[0],m[1],m[2],m[3]};
    int beg = g_off[n], end = g_off[n+1];
    for (int i=beg+lane; i<end; i+=32){
        int s = g_esrc[i];
        float4 av = *(const float4*)&g_as[s*4];
        m[0]=fmaxf(m[0], leaky(av.x+adv.x));
        m[1]=fmaxf(m[1], leaky(av.y+adv.y));
        m[2]=fmaxf(m[2], leaky(av.z+adv.z));
        m[3]=fmaxf(m[3], leaky(av.w+adv.w));
    }
    #pragma unroll
    for (int off=16; off; off>>=1)
        #pragma unroll
        for (int h=0;h<4;h++) m[h] = fmaxf(m[h], __shfl_xor_sync(0xffffffff, m[h], off));
    // chain 0 seeded with self-loop; chain 1 starts at zero
    float den[2][4], accA[2][4], accB[2][4];
    const float* xn = &g_xh[(size_t)n*256];
    #pragma unroll
    for (int h=0;h<4;h++){
        float w = __expf(self[h] - m[h]);
        den[0][h] = w;
        accA[0][h] = w * xn[h*64 + lane];
        accB[0][h] = w * xn[h*64 + 32 + lane];
        den[1][h] = 0.f; accA[1][h] = 0.f; accB[1][h] = 0.f;
    }
    int i = beg;
    for (; i+1 < end; i += 2){
        int s0 = g_esrc[i], s1 = g_esrc[i+1];
        float4 av0 = *(const float4*)&g_as[s0*4];
        float4 av1 = *(const float4*)&g_as[s1*4];
        const float* xs0 = &g_xh[(size_t)s0*256];
        const float* xs1 = &g_xh[(size_t)s1*256];
        float w0[4], w1[4];
        w0[0] = __expf(leaky(av0.x+adv.x) - m[0]);
        w0[1] = __expf(leaky(av0.y+adv.y) - m[1]);
        w0[2] = __expf(leaky(av0.z+adv.z) - m[2]);
        w0[3] = __expf(leaky(av0.w+adv.w) - m[3]);
        w1[0] = __expf(leaky(av1.x+adv.x) - m[0]);
        w1[1] = __expf(leaky(av1.y+adv.y) - m[1]);
        w1[2] = __expf(leaky(av1.z+adv.z) - m[2]);
        w1[3] = __expf(leaky(av1.w+adv.w) - m[3]);
        #pragma unroll
        for (int h=0;h<4;h++){
            den[0][h] += w0[h];
            den[1][h] += w1[h];
            accA[0][h] = fmaf(w0[h], xs0[h*64+lane],    accA[0][h]);
            accA[1][h] = fmaf(w1[h], xs1[h*64+lane],    accA[1][h]);
            accB[0][h] = fmaf(w0[h], xs0[h*64+32+lane], accB[0][h]);
            accB[1][h] = fmaf(w1[h], xs1[h*64+32+lane], accB[1][h]);
        }
    }
    if (i < end){
        int s = g_esrc[i];
        float4 av = *(const float4*)&g_as[s*4];
        const float* xs = &g_xh[(size_t)s*256];
        #pragma unroll
        for (int h=0;h<4;h++){
            float aw;
            if (h==0) aw = leaky(av.x+adv.x);
            else if (h==1) aw = leaky(av.y+adv.y);
            else if (h==2) aw = leaky(av.z+adv.z);
            else aw = leaky(av.w+adv.w);
            float w = __expf(aw - m[h]);
            den[0][h] += w;
            accA[0][h] = fmaf(w, xs[h*64+lane],    accA[0][h]);
            accB[0][h] = fmaf(w, xs[h*64+32+lane], accB[0][h]);
        }
    }
    float rA = 0.f, rB = 0.f;
    #pragma unroll
    for (int h=0;h<4;h++){
        float inv = __fdividef(1.f, den[0][h] + den[1][h]);
        rA += (accA[0][h] + accA[1][h])*inv;
        rB += (accB[0][h] + accB[1][h])*inv;
    }
    g_xgat[n*64 + lane]      = rA*0.25f + sbias[lane];
    g_xgat[n*64 + 32 + lane] = rB*0.25f + sbias[32 + lane];
}

// ---------- K6: P/Q ----------
__global__ void __launch_bounds__(256) k_pq(const float* __restrict__ W1, const float* __restrict__ b1){
    __shared__ float sQf[8192];
    __shared__ float sb1[64];
    for (int i=threadIdx.x; i<8192; i+=256){
        int R = i>>6, k = i&63;
        float v = (R < 64) ? W1[R*130 + k] : W1[(R-64)*130 + 64 + k];
        sQf[((k>>1)*64 + (R>>1))*4 + (R&1) + 2*(k&1)] = v;
    }
    for (int i=threadIdx.x; i<64; i+=256) sb1[i]=b1[i];
    __syncthreads();
    int n = blockIdx.x*256 + threadIdx.x;
    if (n >= Nn) return;

    float xg[64];
    {
        const float4* xv = (const float4*)(g_xgat + n*64);
        #pragma unroll
        for (int i=0;i<16;i++){
            float4 v = xv[i];
            xg[4*i]=v.x; xg[4*i+1]=v.y; xg[4*i+2]=v.z; xg[4*i+3]=v.w;
        }
    }
    const ulonglong2* sQ2 = (const ulonglong2*)sQf;
    #pragma unroll 1
    for (int rb=0; rb<8; rb++){
        u64 acc[8];
        #pragma unroll
        for (int p=0;p<8;p++){
            int r = rb*16 + 2*p;
            acc[p] = (rb < 4) ? pk2(sb1[r], sb1[r+1]) : 0ull;
        }
        #pragma unroll
        for (int k2=0; k2<32; k2++){
            u64 xlo = dup2(xg[2*k2]);
            u64 xhi = dup2(xg[2*k2+1]);
            #pragma unroll
            for (int p=0;p<8;p++){
                ulonglong2 q = sQ2[k2*64 + rb*8 + p];
                fma2(acc[p], xlo, q.x);
                fma2(acc[p], xhi, q.y);
            }
        }
        float v[16];
        #pragma unroll
        for (int p=0;p<8;p++) up2(acc[p], v[2*p], v[2*p+1]);
        float* dst = (rb < 4) ? (g_P + n*64 + rb*16) : (g_Q + n*64 + (rb-4)*16);
        float4* d4 = (float4*)dst;
        d4[0] = make_float4(v[0],v[1],v[2],v[3]);
        d4[1] = make_float4(v[4],v[5],v[6],v[7]);
        d4[2] = make_float4(v[8],v[9],v[10],v[11]);
        d4[3] = make_float4(v[12],v[13],v[14],v[15]);
    }
}

// ---------- K7: edge MLP -> e_lat (streaming) ----------
__global__ void __launch_bounds__(256) k_edge_mlp(
        const int* __restrict__ ei, const float* __restrict__ ea,
        const float* __restrict__ W1, const float* __restrict__ W2,
        const float* __restrict__ b2){
    __shared__ float sW2dq[32*33*4];
    __shared__ float sw128[64], sw129[64], sb2[32];
    extern __shared__ float sHf[];
    for (int i=threadIdx.x; i<2048; i+=256){
        int l = i>>6, j = i&63;
        float v = W2[l*64+j];
        int base = (l*33 + (j>>1))*4 + 2*(j&1);
        sW2dq[base] = v; sW2dq[base+1] = v;
    }
    for (int i=threadIdx.x; i<64; i+=256){
        sw128[i]=W1[i*130+128]; sw129[i]=W1[i*130+129];
    }
    if (threadIdx.x < 32) sb2[threadIdx.x]=b2[threadIdx.x];
    __syncthreads();
    int warp = threadIdx.x>>5, lane = threadIdx.x&31;
    int base_e = (blockIdx.x*8 + warp)*16;
    if (base_e >= Ee) return;

    float* myH = sHf + warp*1024;
    for (int el=0; el<16; el++){
        int e = base_e + el;
        int s = ei[e], d = ei[Ee+e];
        float2 ev = ((const float2*)ea)[e];
        float h0 = fmaxf(g_P[s*64+lane]    + g_Q[d*64+lane]    + ev.x*sw128[lane]    + ev.y*sw129[lane],    0.f);
        float h1 = fmaxf(g_P[s*64+32+lane] + g_Q[d*64+32+lane] + ev.x*sw128[32+lane] + ev.y*sw129[32+lane], 0.f);
        int ep = el>>1, c = el&1;
        int j = lane;
        myH[(ep*32 + (j>>1))*4 + 2*(j&1) + c] = h0;
        j = lane + 32;
        myH[(ep*32 + (j>>1))*4 + 2*(j&1) + c] = h1;
    }
    __syncwarp();
    u64 acc[8];
    #pragma unroll
    for (int ep=0;ep<8;ep++) acc[ep] = dup2(sb2[lane]);
    const ulonglong2* sW2q = (const ulonglong2*)sW2dq;
    const ulonglong2* sH2 = (const ulonglong2*)myH;
    #pragma unroll 4
    for (int j2=0; j2<32; j2++){
        ulonglong2 qw = sW2q[lane*33 + j2];
        #pragma unroll
        for (int ep=0;ep<8;ep++){
            ulonglong2 xq = sH2[ep*32 + j2];
            fma2(acc[ep], xq.x, qw.x);
            fma2(acc[ep], xq.y, qw.y);
        }
    }
    #pragma unroll
    for (int ep=0;ep<8;ep++){
        float o0, o1;
        up2(acc[ep], o0, o1);
        g_elat[(base_e + 2*ep)*32 + lane]   = o0;
        g_elat[(base_e + 2*ep+1)*32 + lane] = o1;
    }
}

// ---------- K8: agg gather (unroll-2 dual accumulators) ----------
__global__ void __launch_bounds__(256) k_agg_gather(){
    int warp = threadIdx.x>>5, lane = threadIdx.x&31;
    int n = blockIdx.x*8 + warp;
    if (n >= Nn) return;
    int beg = g_off[n], end = g_off[n+1];
    float acc0 = 0.f, acc1 = 0.f;
    int i = beg;
    for (; i+1 < end; i += 2){
        int e0 = g_eid[i], e1 = g_eid[i+1];
        acc0 += g_elat[e0*32 + lane];
        acc1 += g_elat[e1*32 + lane];
    }
    if (i < end) acc0 += g_elat[g_eid[i]*32 + lane];
    g_agg[n*32 + lane] = __fdividef(acc0 + acc1, fmaxf(g_cntf[n], 1.f));
}

// ---------- K9: node MLP ----------
__global__ void __launch_bounds__(128) k_node_mlp(
        const float* __restrict__ W1, const float* __restrict__ b1,
        const float* __restrict__ W2, const float* __restrict__ b2,
        float* __restrict__ outp){
    __shared__ float sQf[6144];
    __shared__ float sW2[256];
    __shared__ float sb1[64];
    for (int i=threadIdx.x; i<6144; i+=128){
        int r = i/96, k = i - r*96;
        sQf[((k>>1)*32 + (r>>1))*4 + (r&1) + 2*(k&1)] = W1[i];
    }
    for (int i=threadIdx.x; i<256; i+=128) sW2[i]=W2[i];
    for (int i=threadIdx.x; i<64;  i+=128) sb1[i]=b1[i];
    __syncthreads();
    int n = blockIdx.x*128 + threadIdx.x;
    if (n >= Nn) return;

    float xc[96];
    {
        const float4* xv = (const float4*)(g_xgat + n*64);
        #pragma unroll
        for (int i=0;i<16;i++){
            float4 v = xv[i];
            xc[4*i]=v.x; xc[4*i+1]=v.y; xc[4*i+2]=v.z; xc[4*i+3]=v.w;
        }
        const float4* av = (const float4*)(g_agg + n*32);
        #pragma unroll
        for (int i=0;i<8;i++){
            float4 v = av[i];
            xc[64+4*i]=v.x; xc[64+4*i+1]=v.y; xc[64+4*i+2]=v.z; xc[64+4*i+3]=v.w;
        }
    }
    const ulonglong2* sQ2 = (const ulonglong2*)sQf;
    float p[4] = {0,0,0,0};
    #pragma unroll 1
    for (int rb=0; rb<4; rb++){
        u64 acc[8];
        #pragma unroll
        for (int q=0;q<8;q++){
            int r = rb*16 + 2*q;
            acc[q] = pk2(sb1[r], sb1[r+1]);
        }
        #pragma unroll
        for (int k2=0; k2<48; k2++){
            u64 xlo = dup2(xc[2*k2]);
            u64 xhi = dup2(xc[2*k2+1]);
            #pragma unroll
            for (int q=0;q<8;q++){
                ulonglong2 w = sQ2[k2*32 + rb*8 + q];
                fma2(acc[q], xlo, w.x);
                fma2(acc[q], xhi, w.y);
            }
        }
        #pragma unroll
        for (int q=0;q<8;q++){
            float vlo, vhi;
            up2(acc[q], vlo, vhi);
            int r = rb*16 + 2*q;
            vlo = fmaxf(vlo, 0.f); vhi = fmaxf(vhi, 0.f);
            #pragma unroll
            for (int o=0;o<4;o++)
                p[o] += vlo*sW2[o*64 + r] + vhi*sW2[o*64 + r + 1];
        }
    }
    *(float4*)&outp[OUT_OFF + n*4] = make_float4(p[0]+b2[0], p[1]+b2[1], p[2]+b2[2], p[3]+b2[3]);
}

extern "C" void kernel_launch(void* const* d_in, const int* in_sizes, int n_in,
                              void* d_out, int out_size){
    (void)in_sizes; (void)n_in; (void)out_size;
    const float* x    = (const float*)d_in[0];
    const int*   ei   = (const int*)  d_in[1];
    const float* ea   = (const float*)d_in[2];
    const float* hnh  = (const float*)d_in[3];
    const float* hnc  = (const float*)d_in[4];
    const float* heh  = (const float*)d_in[5];
    const float* hec  = (const float*)d_in[6];
    const float* nWih = (const float*)d_in[7];
    const float* nWhh = (const float*)d_in[8];
    const float* nb   = (const float*)d_in[9];
    const float* eWih = (const float*)d_in[10];
    const float* eWhh = (const float*)d_in[11];
    const float* eb   = (const float*)d_in[12];
    const float* gatW = (const float*)d_in[13];
    const float* attS = (const float*)d_in[14];
    const float* attD = (const float*)d_in[15];
    const float* gatB = (const float*)d_in[16];
    const float* emW1 = (const float*)d_in[17];
    const float* emb1 = (const float*)d_in[18];
    const float* emW2 = (const float*)d_in[19];
    const float* emb2 = (const float*)d_in[20];
    const float* nmW1 = (const float*)d_in[21];
    const float* nmb1 = (const float*)d_in[22];
    const float* nmW2 = (const float*)d_in[23];
    const float* nmb2 = (const float*)d_in[24];
    float* out = (float*)d_out;

    static const int elstm_smem = (4480 + 4*4096)*4;             // 83456
    static const int nlstm_smem = (16384 + 1280 + 256)*4;        // 71680
    static const int gproj_smem = (24576 + 512)*4;               // 100352
    static const int emlp_smem  = 8192*4;                        // 32768

    static bool init_done = false;
    static cudaStream_t sB;
    static cudaEvent_t evFork, evJoin;
    if (!init_done){
        cudaFuncSetAttribute(k_edge_lstm, cudaFuncAttributeMaxDynamicSharedMemorySize, elstm_smem);
        cudaFuncSetAttribute(k_node_lstm, cudaFuncAttributeMaxDynamicSharedMemorySize, nlstm_smem);
        cudaFuncSetAttribute(k_gat_proj,  cudaFuncAttributeMaxDynamicSharedMemorySize, gproj_smem);
        cudaFuncSetAttribute(k_edge_mlp,  cudaFuncAttributeMaxDynamicSharedMemorySize, emlp_smem);
        cudaStreamCreateWithFlags(&sB, cudaStreamNonBlocking);
        cudaEventCreateWithFlags(&evFork, cudaEventDisableTiming);
        cudaEventCreateWithFlags(&evJoin, cudaEventDisableTiming);
        init_done = true;
    }

    // fork side stream B off the origin stream
    cudaEventRecord(evFork, 0);
    cudaStreamWaitEvent(sB, evFork, 0);

    // stream B: CSR build + node LSTM (independent of edge LSTM)
    k_zero_cnt<<<NBLK, 256, 0, sB>>>();
    k_count<<<(Ee+255)/256, 256, 0, sB>>>(ei);
    k_scan1<<<NBLK, 256, 0, sB>>>();

    // origin stream: edge LSTM (ncu capture slot)
    k_edge_lstm<<<(Ee/64 + 3)/4, 128, elstm_smem>>>(ea, heh, hec, eWih, eWhh, eb, out);

    k_scan2<<<1, 256, 0, sB>>>();
    k_scan3<<<NBLK, 256, 0, sB>>>();
    k_bin<<<(Ee+255)/256, 256, 0, sB>>>(ei);
    k_node_lstm<<<(Nn+127)/128, 128, nlstm_smem, sB>>>(x, hnh, hnc, nWih, nWhh, nb, out);

    // join
    cudaEventRecord(evJoin, sB);
    cudaStreamWaitEvent(0, evJoin, 0);

    // serial tail on origin stream
    k_enc_gather<<<(Nn+7)/8, 256>>>(out);
    k_gat_proj<<<(Nn+127)/128, 128, gproj_smem>>>(gatW, attS, attD);
    k_gat_fused<<<(Nn+7)/8, 256>>>(gatB);
    k_pq<<<(Nn+255)/256, 256>>>(emW1, emb1);
    k_edge_mlp<<<(Ee+127)/128, 256, emlp_smem>>>(ei, ea, emW1, emW2, emb2);
    k_agg_gather<<<(Nn+7)/8, 256>>>();
    k_node_mlp<<<(Nn+127)/128, 128>>>(nmW1, nmb1, nmW2, nmb2, out);
}

// round 15
// speedup vs baseline: 1.0609x; 1.0543x over previous
#include <cuda_runtime.h>
#include <math.h>

#define Nn 50000
#define Ee 400000
#define NBLK 196   // ceil(Nn/256)

// output packing: out[N*4], nh[N*64], nc[N*64], eh[E*32], ec[E*32]
#define OUT_OFF 0
#define NH_OFF  (Nn*4)
#define NC_OFF  (NH_OFF + Nn*64)
#define EH_OFF  (NC_OFF + Nn*64)
#define EC_OFF  (EH_OFF + Ee*32)

// ---------------- scratch ----------------
__device__ int   g_cnti[Nn];
__device__ int   g_bsum[256];
__device__ int   g_boff[256];
__device__ int   g_off[Nn+1];
__device__ int   g_cursor[Nn];
__device__ int   g_eid[Ee];
__device__ int   g_esrc[Ee];
__device__ float g_cntf[Nn];
__device__ float g_xcat[Nn*96];
__device__ float g_xh[Nn*256];
__device__ float g_as[Nn*4];
__device__ float g_ad[Nn*4];
__device__ float g_xgat[Nn*64];
__device__ float g_P[Nn*64];
__device__ float g_Q[Nn*64];
__device__ float g_elat[Ee*32];
__device__ float g_agg[Nn*32];

typedef unsigned long long u64;
__device__ __forceinline__ u64 pk2(float lo, float hi){ u64 r; asm("mov.b64 %0, {%1,%2};" : "=l"(r) : "f"(lo), "f"(hi)); return r; }
__device__ __forceinline__ u64 dup2(float v){ return pk2(v,v); }
__device__ __forceinline__ void fma2(u64 &acc, u64 a, u64 b){ asm("fma.rn.f32x2 %0, %1, %2, %0;" : "+l"(acc) : "l"(a), "l"(b)); }
__device__ __forceinline__ void up2(u64 v, float &lo, float &hi){ asm("mov.b64 {%0,%1}, %2;" : "=f"(lo), "=f"(hi) : "l"(v)); }

__device__ __forceinline__ float tanha(float x){ float r; asm("tanh.approx.f32 %0, %1;" : "=f"(r) : "f"(x)); return r; }
__device__ __forceinline__ float fsig(float x){ return fmaf(0.5f, tanha(0.5f*x), 0.5f); }
__device__ __forceinline__ float leaky(float x){ return x > 0.f ? x : 0.2f*x; }

// ================= CSR build =================
__global__ void k_zero_cnt(){
    int t = blockIdx.x*blockDim.x + threadIdx.x;
    if (t < Nn) g_cnti[t] = 0;
}
__global__ void k_count(const int* __restrict__ ei){
    int e = blockIdx.x*blockDim.x + threadIdx.x;
    if (e < Ee) atomicAdd(&g_cnti[ei[Ee+e]], 1);
}
__global__ void k_scan1(){
    __shared__ int s[256];
    int i = blockIdx.x*256 + threadIdx.x;
    s[threadIdx.x] = (i < Nn) ? g_cnti[i] : 0;
    __syncthreads();
    for (int o=128; o; o>>=1){
        if (threadIdx.x < o) s[threadIdx.x] += s[threadIdx.x+o];
        __syncthreads();
    }
    if (threadIdx.x == 0) g_bsum[blockIdx.x] = s[0];
}
__global__ void k_scan2(){
    __shared__ int s[256];
    int t = threadIdx.x;
    s[t] = (t < NBLK) ? g_bsum[t] : 0;
    __syncthreads();
    if (t == 0){
        int run = 0;
        for (int i=0;i<NBLK;i++){ int v=s[i]; s[i]=run; run+=v; }
    }
    __syncthreads();
    if (t < NBLK) g_boff[t] = s[t];
}
__global__ void k_scan3(){
    __shared__ int s[256];
    int t = threadIdx.x;
    int i = blockIdx.x*256 + t;
    int cnt = (i < Nn) ? g_cnti[i] : 0;
    s[t] = cnt;
    __syncthreads();
    for (int o=1; o<256; o<<=1){
        int v = (t >= o) ? s[t-o] : 0;
        __syncthreads();
        s[t] += v;
        __syncthreads();
    }
    int off = g_boff[blockIdx.x] + s[t] - cnt;
    if (i < Nn){
        g_off[i] = off;
        g_cursor[i] = off;
        g_cntf[i] = (float)cnt;
        if (i == Nn-1) g_off[Nn] = off + cnt;
    }
}
__global__ void k_bin(const int* __restrict__ ei){
    int e = blockIdx.x*blockDim.x + threadIdx.x;
    if (e >= Ee) return;
    int d = ei[Ee+e];
    int p = atomicAdd(&g_cursor[d], 1);
    g_eid[p]  = e;
    g_esrc[p] = ei[e];
}

// ---------- K1: edge LSTM — 2 edges/thread, 4 warps/block ----------
__global__ void __launch_bounds__(128) k_edge_lstm(
        const float* __restrict__ ea,
        const float* __restrict__ h0, const float* __restrict__ c0,
        const float* __restrict__ Wih, const float* __restrict__ Whh,
        const float* __restrict__ b, float* __restrict__ outp){
    extern __shared__ float dyn[];
    float* sQf  = dyn;
    float* sWih = dyn + 4096;
    float* sb   = dyn + 4352;
    for (int i=threadIdx.x; i<4096; i+=128){
        int r = i>>5, k = i&31;
        sQf[((k>>1)*64 + (r>>1))*4 + (r&1) + 2*(k&1)] = Whh[i];
    }
    for (int i=threadIdx.x; i<256; i+=128) sWih[i] = Wih[i];
    for (int i=threadIdx.x; i<128; i+=128) sb[i] = b[i];
    __syncthreads();

    int warp = threadIdx.x>>5, lane = threadIdx.x&31;
    int e0 = (blockIdx.x*4 + warp)*64;
    if (e0 >= Ee) return;
    float* mH = dyn + 4480 + warp*4096;
    float* mC = mH + 2048;

    {
        const float4* gh = (const float4*)(h0 + (size_t)e0*32);
        const float4* gc = (const float4*)(c0 + (size_t)e0*32);
        #pragma unroll
        for (int i=0;i<16;i++){
            int j = lane + 32*i;
            int e = j>>3, q = j&7;
            int slot = e*32 + ((q ^ (e&7))<<2);
            *(float4*)&mH[slot] = gh[j];
            *(float4*)&mC[slot] = gc[j];
        }
    }
    __syncwarp();

    float h[2][32];
    #pragma unroll
    for (int u=0;u<2;u++){
        int row = lane + 32*u;
        #pragma unroll
        for (int i=0;i<8;i++){
            float4 v = *(float4*)&mH[row*32 + ((i ^ (row&7))<<2)];
            h[u][4*i]=v.x; h[u][4*i+1]=v.y; h[u][4*i+2]=v.z; h[u][4*i+3]=v.w;
        }
    }
    float2 xv[2];
    xv[0] = ((const float2*)ea)[e0 + lane];
    xv[1] = ((const float2*)ea)[e0 + 32 + lane];
    const ulonglong2* sQ2 = (const ulonglong2*)sQf;

    #pragma unroll 1
    for (int j0=0;j0<32;j0+=4){
        u64 acc[2][4][2];
        #pragma unroll
        for (int u=0;u<2;u++)
            #pragma unroll
            for (int g=0; g<4; g++)
                #pragma unroll
                for (int p=0; p<2; p++){
                    int r0 = g*32 + j0 + 2*p;
                    float alo = sb[r0]   + xv[u].x*sWih[2*r0]   + xv[u].y*sWih[2*r0+1];
                    float ahi = sb[r0+1] + xv[u].x*sWih[2*r0+2] + xv[u].y*sWih[2*r0+3];
                    acc[u][g][p] = pk2(alo, ahi);
                }
        #pragma unroll
        for (int k2=0; k2<16; k2++){
            u64 x0lo = dup2(h[0][2*k2]), x0hi = dup2(h[0][2*k2+1]);
            u64 x1lo = dup2(h[1][2*k2]), x1hi = dup2(h[1][2*k2+1]);
            #pragma unroll
            for (int g=0; g<4; g++)
                #pragma unroll
                for (int p=0; p<2; p++){
                    ulonglong2 q = sQ2[k2*64 + g*16 + (j0>>1) + p];
                    fma2(acc[0][g][p], x0lo, q.x);
                    fma2(acc[0][g][p], x0hi, q.y);
                    fma2(acc[1][g][p], x1lo, q.x);
                    fma2(acc[1][g][p], x1hi, q.y);
                }
        }
        #pragma unroll
        for (int u=0;u<2;u++){
            float gi[4], gf[4], gg[4], go[4];
            #pragma unroll
            for (int p=0; p<2; p++){
                up2(acc[u][0][p], gi[2*p], gi[2*p+1]);
                up2(acc[u][1][p], gf[2*p], gf[2*p+1]);
                up2(acc[u][2][p], gg[2*p], gg[2*p+1]);
                up2(acc[u][3][p], go[2*p], go[2*p+1]);
            }
            int row = lane + 32*u;
            int slot = row*32 + (((j0>>2) ^ (row&7))<<2);
            float4 cv = *(float4*)&mC[slot];
            float cc[4] = {cv.x, cv.y, cv.z, cv.w};
            float h2a[4], c2a[4];
            #pragma unroll
            for (int t=0; t<4; t++){
                float c2 = fsig(gf[t])*cc[t] + fsig(gi[t])*tanha(gg[t]);
                float h2 = fsig(go[t])*tanha(c2);
                h2a[t]=h2; c2a[t]=c2;
            }
            *(float4*)&mH[slot] = make_float4(h2a[0],h2a[1],h2a[2],h2a[3]);
            *(float4*)&mC[slot] = make_float4(c2a[0],c2a[1],c2a[2],c2a[3]);
        }
    }
    __syncwarp();
    {
        float4* geh = (float4*)(outp + EH_OFF + (size_t)e0*32);
        float4* gec = (float4*)(outp + EC_OFF + (size_t)e0*32);
        #pragma unroll
        for (int i=0;i<16;i++){
            int j = lane + 32*i;
            int e = j>>3, q = j&7;
            int slot = e*32 + ((q ^ (e&7))<<2);
            geh[j] = *(float4*)&mH[slot];
            gec[j] = *(float4*)&mC[slot];
        }
    }
}

// ---------- K2: node LSTM ----------
__global__ void __launch_bounds__(128) k_node_lstm(
        const float* __restrict__ x, const float* __restrict__ h0,
        const float* __restrict__ c0, const float* __restrict__ Wih,
        const float* __restrict__ Whh, const float* __restrict__ b,
        float* __restrict__ outp){
    extern __shared__ float dyn[];
    float* sQf  = dyn;
    float* sWih = dyn + 16384;
    float* sb   = sWih + 1280;
    for (int i=threadIdx.x; i<16384; i+=128){
        int r = i>>6, k = i&63;
        sQf[((k>>1)*128 + (r>>1))*4 + (r&1) + 2*(k&1)] = Whh[i];
    }
    for (int i=threadIdx.x; i<1280; i+=128) sWih[i] = Wih[i];
    for (int i=threadIdx.x; i<256;  i+=128) sb[i] = b[i];
    __syncthreads();
    int node = blockIdx.x*128 + threadIdx.x;
    if (node >= Nn) return;

    float xr[5];
    #pragma unroll
    for (int k=0;k<5;k++) xr[k] = x[node*5+k];
    float h[64];
    {
        const float4* h0v = (const float4*)h0;
        #pragma unroll
        for (int i=0;i<16;i++){
            float4 v = h0v[node*16+i];
            h[4*i]=v.x; h[4*i+1]=v.y; h[4*i+2]=v.z; h[4*i+3]=v.w;
        }
    }
    const float4* c0v = (const float4*)c0;
    float4* outv = (float4*)outp;
    const ulonglong2* sQ2 = (const ulonglong2*)sQf;

    #pragma unroll 1
    for (int j0=0;j0<64;j0+=4){
        u64 acc[4][2];
        #pragma unroll
        for (int g=0; g<4; g++)
            #pragma unroll
            for (int p=0; p<2; p++){
                int r0 = g*64 + j0 + 2*p;
                float alo = sb[r0], ahi = sb[r0+1];
                #pragma unroll
                for (int k=0;k<5;k++){
                    alo += xr[k]*sWih[r0*5+k];
                    ahi += xr[k]*sWih[(r0+1)*5+k];
                }
                acc[g][p] = pk2(alo, ahi);
            }
        #pragma unroll
        for (int k2=0; k2<32; k2++){
            u64 xlo = dup2(h[2*k2]);
            u64 xhi = dup2(h[2*k2+1]);
            #pragma unroll
            for (int g=0; g<4; g++)
                #pragma unroll
                for (int p=0; p<2; p++){
                    ulonglong2 q = sQ2[k2*128 + g*32 + (j0>>1) + p];
                    fma2(acc[g][p], xlo, q.x);
                    fma2(acc[g][p], xhi, q.y);
                }
        }
        float gi[4], gf[4], gg[4], go[4];
        #pragma unroll
        for (int p=0; p<2; p++){
            up2(acc[0][p], gi[2*p], gi[2*p+1]);
            up2(acc[1][p], gf[2*p], gf[2*p+1]);
            up2(acc[2][p], gg[2*p], gg[2*p+1]);
            up2(acc[3][p], go[2*p], go[2*p+1]);
        }
        float4 cv = c0v[node*16 + (j0>>2)];
        float cc[4] = {cv.x, cv.y, cv.z, cv.w};
        float h2a[4], c2a[4];
        #pragma unroll
        for (int u=0; u<4; u++){
            float c2 = fsig(gf[u])*cc[u] + fsig(gi[u])*tanha(gg[u]);
            float h2 = fsig(go[u])*tanha(c2);
            h2a[u]=h2; c2a[u]=c2;
        }
        float4 h2v = make_float4(h2a[0],h2a[1],h2a[2],h2a[3]);
        outv[(NH_OFF + node*64 + j0)>>2] = h2v;
        outv[(NC_OFF + node*64 + j0)>>2] = make_float4(c2a[0],c2a[1],c2a[2],c2a[3]);
        ((float4*)g_xcat)[(node*96 + j0)>>2] = h2v;
    }
}

// ---------- K3: enc gather ----------
__global__ void __launch_bounds__(256) k_enc_gather(const float* __restrict__ outp){
    int warp = threadIdx.x>>5, lane = threadIdx.x&31;
    int n = blockIdx.x*8 + warp;
    if (n >= Nn) return;
    int beg = g_off[n], end = g_off[n+1];
    float acc = 0.f;
    for (int i=beg; i<end; i++){
        int e = g_eid[i];
        acc += outp[EH_OFF + e*32 + lane];
    }
    g_xcat[n*96 + 64 + lane] = __fdividef(acc, fmaxf(g_cntf[n], 1.f));
}

// ---------- K4: GAT projection + logits ----------
__global__ void __launch_bounds__(128) k_gat_proj(const float* __restrict__ W,
                                                  const float* __restrict__ att_s,
                                                  const float* __restrict__ att_d){
    extern __shared__ float dyn[];
    float* sQf = dyn;
    float* ss  = dyn + 24576;
    float* sd  = ss + 256;
    for (int i=threadIdx.x; i<24576; i+=128){
        int r = i/96, k = i - r*96;
        sQf[((k>>1)*128 + (r>>1))*4 + (r&1) + 2*(k&1)] = W[i];
    }
    for (int i=threadIdx.x; i<256; i+=128){ ss[i]=att_s[i]; sd[i]=att_d[i]; }
    __syncthreads();
    int n = blockIdx.x*128 + threadIdx.x;
    if (n >= Nn) return;

    float xc[96];
    {
        const float4* xv = (const float4*)(g_xcat + n*96);
        #pragma unroll
        for (int i=0;i<24;i++){
            float4 v = xv[i];
            xc[4*i]=v.x; xc[4*i+1]=v.y; xc[4*i+2]=v.z; xc[4*i+3]=v.w;
        }
    }
    const ulonglong2* sQ2 = (const ulonglong2*)sQf;
    float asa[4] = {0,0,0,0}, ada[4] = {0,0,0,0};

    #pragma unroll 1
    for (int rb=0; rb<16; rb++){
        u64 acc[8];
        #pragma unroll
        for (int p=0;p<8;p++) acc[p] = 0ull;
        #pragma unroll
        for (int k2=0; k2<48; k2++){
            u64 xlo = dup2(xc[2*k2]);
            u64 xhi = dup2(xc[2*k2+1]);
            #pragma unroll
            for (int p=0;p<8;p++){
                ulonglong2 q = sQ2[k2*128 + rb*8 + p];
                fma2(acc[p], xlo, q.x);
                fma2(acc[p], xhi, q.y);
            }
        }
        float v[16];
        #pragma unroll
        for (int p=0;p<8;p++) up2(acc[p], v[2*p], v[2*p+1]);
        int hd = rb>>2;
        #pragma unroll
        for (int u=0;u<16;u++){
            int r = rb*16 + u;
            asa[hd] += v[u]*ss[r];
            ada[hd] += v[u]*sd[r];
        }
        float4* xh4 = (float4*)(g_xh + (size_t)n*256 + rb*16);
        xh4[0] = make_float4(v[0],v[1],v[2],v[3]);
        xh4[1] = make_float4(v[4],v[5],v[6],v[7]);
        xh4[2] = make_float4(v[8],v[9],v[10],v[11]);
        xh4[3] = make_float4(v[12],v[13],v[14],v[15]);
    }
    *(float4*)&g_as[n*4] = make_float4(asa[0],asa[1],asa[2],asa[3]);
    *(float4*)&g_ad[n*4] = make_float4(ada[0],ada[1],ada[2],ada[3]);
}

// ---------- K5: fused GAT softmax+aggregate (warp/dst, two-pass) ----------
__global__ void __launch_bounds__(256) k_gat_fused(const float* __restrict__ bias){
    __shared__ float sbias[64];
    if (threadIdx.x < 64) sbias[threadIdx.x] = bias[threadIdx.x];
    __syncthreads();
    int warp = threadIdx.x>>5, lane = threadIdx.x&31;
    int n = blockIdx.x*8 + warp;
    if (n >= Nn) return;
    float4 adv = *(const float4*)&g_ad[n*4];
    float4 asv = *(const float4*)&g_as[n*4];
    float m[4];
    m[0]=leaky(asv.x+adv.x); m[1]=leaky(asv.y+adv.y);
    m[2]=leaky(asv.z+adv.z); m[3]=leaky(asv.w+adv.w);
    float self[4] = {m[0],m[1],m[2],m[3]};
    int beg = g_off[n], end = g_off[n+1];
    for (int i=beg+lane; i<end; i+=32){
        int s = g_esrc[i];
        float4 av = *(const float4*)&g_as[s*4];
        m[0]=fmaxf(m[0], leaky(av.x+adv.x));
        m[1]=fmaxf(m[1], leaky(av.y+adv.y));
        m[2]=fmaxf(m[2], leaky(av.z+adv.z));
        m[3]=fmaxf(m[3], leaky(av.w+adv.w));
    }
    #pragma unroll
    for (int off=16; off; off>>=1)
        #pragma unroll
        for (int h=0;h<4;h++) m[h] = fmaxf(m[h], __shfl_xor_sync(0xffffffff, m[h], off));
    float den[4], accA[4], accB[4];
    const float* xn = &g_xh[(size_t)n*256];
    #pragma unroll
    for (int h=0;h<4;h++){
        float w = __expf(self[h] - m[h]);
        den[h] = w;
        accA[h] = w * xn[h*64 + lane];
        accB[h] = w * xn[h*64 + 32 + lane];
    }
    for (int i=beg; i<end; i++){
        int s = g_esrc[i];
        float4 av = *(const float4*)&g_as[s*4];
        float w0 = __expf(leaky(av.x+adv.x) - m[0]);
        float w1 = __expf(leaky(av.y+adv.y) - m[1]);
        float w2 = __expf(leaky(av.z+adv.z) - m[2]);
        float w3 = __expf(leaky(av.w+adv.w) - m[3]);
        den[0]+=w0; den[1]+=w1; den[2]+=w2; den[3]+=w3;
        const float* xs = &g_xh[(size_t)s*256];
        accA[0] += w0*xs[lane];       accB[0] += w0*xs[32+lane];
        accA[1] += w1*xs[64+lane];    accB[1] += w1*xs[96+lane];
        accA[2] += w2*xs[128+lane];   accB[2] += w2*xs[160+lane];
        accA[3] += w3*xs[192+lane];   accB[3] += w3*xs[224+lane];
    }
    float rA = 0.f, rB = 0.f;
    #pragma unroll
    for (int h=0;h<4;h++){
        float inv = __fdividef(1.f, den[h]);
        rA += accA[h]*inv;
        rB += accB[h]*inv;
    }
    g_xgat[n*64 + lane]      = rA*0.25f + sbias[lane];
    g_xgat[n*64 + 32 + lane] = rB*0.25f + sbias[32 + lane];
}

// ---------- K6: P/Q ----------
__global__ void __launch_bounds__(256) k_pq(const float* __restrict__ W1, const float* __restrict__ b1){
    __shared__ float sQf[8192];
    __shared__ float sb1[64];
    for (int i=threadIdx.x; i<8192; i+=256){
        int R = i>>6, k = i&63;
        float v = (R < 64) ? W1[R*130 + k] : W1[(R-64)*130 + 64 + k];
        sQf[((k>>1)*64 + (R>>1))*4 + (R&1) + 2*(k&1)] = v;
    }
    for (int i=threadIdx.x; i<64; i+=256) sb1[i]=b1[i];
    __syncthreads();
    int n = blockIdx.x*256 + threadIdx.x;
    if (n >= Nn) return;

    float xg[64];
    {
        const float4* xv = (const float4*)(g_xgat + n*64);
        #pragma unroll
        for (int i=0;i<16;i++){
            float4 v = xv[i];
            xg[4*i]=v.x; xg[4*i+1]=v.y; xg[4*i+2]=v.z; xg[4*i+3]=v.w;
        }
    }
    const ulonglong2* sQ2 = (const ulonglong2*)sQf;
    #pragma unroll 1
    for (int rb=0; rb<8; rb++){
        u64 acc[8];
        #pragma unroll
        for (int p=0;p<8;p++){
            int r = rb*16 + 2*p;
            acc[p] = (rb < 4) ? pk2(sb1[r], sb1[r+1]) : 0ull;
        }
        #pragma unroll
        for (int k2=0; k2<32; k2++){
            u64 xlo = dup2(xg[2*k2]);
            u64 xhi = dup2(xg[2*k2+1]);
            #pragma unroll
            for (int p=0;p<8;p++){
                ulonglong2 q = sQ2[k2*64 + rb*8 + p];
                fma2(acc[p], xlo, q.x);
                fma2(acc[p], xhi, q.y);
            }
        }
        float v[16];
        #pragma unroll
        for (int p=0;p<8;p++) up2(acc[p], v[2*p], v[2*p+1]);
        float* dst = (rb < 4) ? (g_P + n*64 + rb*16) : (g_Q + n*64 + (rb-4)*16);
        float4* d4 = (float4*)dst;
        d4[0] = make_float4(v[0],v[1],v[2],v[3]);
        d4[1] = make_float4(v[4],v[5],v[6],v[7]);
        d4[2] = make_float4(v[8],v[9],v[10],v[11]);
        d4[3] = make_float4(v[12],v[13],v[14],v[15]);
    }
}

// ---------- K7: edge MLP -> e_lat (streaming) ----------
__global__ void __launch_bounds__(256) k_edge_mlp(
        const int* __restrict__ ei, const float* __restrict__ ea,
        const float* __restrict__ W1, const float* __restrict__ W2,
        const float* __restrict__ b2){
    __shared__ float sW2dq[32*33*4];
    __shared__ float sw128[64], sw129[64], sb2[32];
    extern __shared__ float sHf[];
    for (int i=threadIdx.x; i<2048; i+=256){
        int l = i>>6, j = i&63;
        float v = W2[l*64+j];
        int base = (l*33 + (j>>1))*4 + 2*(j&1);
        sW2dq[base] = v; sW2dq[base+1] = v;
    }
    for (int i=threadIdx.x; i<64; i+=256){
        sw128[i]=W1[i*130+128]; sw129[i]=W1[i*130+129];
    }
    if (threadIdx.x < 32) sb2[threadIdx.x]=b2[threadIdx.x];
    __syncthreads();
    int warp = threadIdx.x>>5, lane = threadIdx.x&31;
    int base_e = (blockIdx.x*8 + warp)*16;
    if (base_e >= Ee) return;

    float* myH = sHf + warp*1024;
    for (int el=0; el<16; el++){
        int e = base_e + el;
        int s = ei[e], d = ei[Ee+e];
        float2 ev = ((const float2*)ea)[e];
        float h0 = fmaxf(g_P[s*64+lane]    + g_Q[d*64+lane]    + ev.x*sw128[lane]    + ev.y*sw129[lane],    0.f);
        float h1 = fmaxf(g_P[s*64+32+lane] + g_Q[d*64+32+lane] + ev.x*sw128[32+lane] + ev.y*sw129[32+lane], 0.f);
        int ep = el>>1, c = el&1;
        int j = lane;
        myH[(ep*32 + (j>>1))*4 + 2*(j&1) + c] = h0;
        j = lane + 32;
        myH[(ep*32 + (j>>1))*4 + 2*(j&1) + c] = h1;
    }
    __syncwarp();
    u64 acc[8];
    #pragma unroll
    for (int ep=0;ep<8;ep++) acc[ep] = dup2(sb2[lane]);
    const ulonglong2* sW2q = (const ulonglong2*)sW2dq;
    const ulonglong2* sH2 = (const ulonglong2*)myH;
    #pragma unroll 4
    for (int j2=0; j2<32; j2++){
        ulonglong2 qw = sW2q[lane*33 + j2];
        #pragma unroll
        for (int ep=0;ep<8;ep++){
            ulonglong2 xq = sH2[ep*32 + j2];
            fma2(acc[ep], xq.x, qw.x);
            fma2(acc[ep], xq.y, qw.y);
        }
    }
    #pragma unroll
    for (int ep=0;ep<8;ep++){
        float o0, o1;
        up2(acc[ep], o0, o1);
        g_elat[(base_e + 2*ep)*32 + lane]   = o0;
        g_elat[(base_e + 2*ep+1)*32 + lane] = o1;
    }
}

// ---------- K8: agg gather ----------
__global__ void __launch_bounds__(256) k_agg_gather(){
    int warp = threadIdx.x>>5, lane = threadIdx.x&31;
    int n = blockIdx.x*8 + warp;
    if (n >= Nn) return;
    int beg = g_off[n], end = g_off[n+1];
    float acc = 0.f;
    for (int i=beg; i<end; i++){
        int e = g_eid[i];
        acc += g_elat[e*32 + lane];
    }
    g_agg[n*32 + lane] = __fdividef(acc, fmaxf(g_cntf[n], 1.f));
}

// ---------- K9: node MLP ----------
__global__ void __launch_bounds__(128) k_node_mlp(
        const float* __restrict__ W1, const float* __restrict__ b1,
        const float* __restrict__ W2, const float* __restrict__ b2,
        float* __restrict__ outp){
    __shared__ float sQf[6144];
    __shared__ float sW2[256];
    __shared__ float sb1[64];
    for (int i=threadIdx.x; i<6144; i+=128){
        int r = i/96, k = i - r*96;
        sQf[((k>>1)*32 + (r>>1))*4 + (r&1) + 2*(k&1)] = W1[i];
    }
    for (int i=threadIdx.x; i<256; i+=128) sW2[i]=W2[i];
    for (int i=threadIdx.x; i<64;  i+=128) sb1[i]=b1[i];
    __syncthreads();
    int n = blockIdx.x*128 + threadIdx.x;
    if (n >= Nn) return;

    float xc[96];
    {
        const float4* xv = (const float4*)(g_xgat + n*64);
        #pragma unroll
        for (int i=0;i<16;i++){
            float4 v = xv[i];
            xc[4*i]=v.x; xc[4*i+1]=v.y; xc[4*i+2]=v.z; xc[4*i+3]=v.w;
        }
        const float4* av = (const float4*)(g_agg + n*32);
        #pragma unroll
        for (int i=0;i<8;i++){
            float4 v = av[i];
            xc[64+4*i]=v.x; xc[64+4*i+1]=v.y; xc[64+4*i+2]=v.z; xc[64+4*i+3]=v.w;
        }
    }
    const ulonglong2* sQ2 = (const ulonglong2*)sQf;
    float p[4] = {0,0,0,0};
    #pragma unroll 1
    for (int rb=0; rb<4; rb++){
        u64 acc[8];
        #pragma unroll
        for (int q=0;q<8;q++){
            int r = rb*16 + 2*q;
            acc[q] = pk2(sb1[r], sb1[r+1]);
        }
        #pragma unroll
        for (int k2=0; k2<48; k2++){
            u64 xlo = dup2(xc[2*k2]);
            u64 xhi = dup2(xc[2*k2+1]);
            #pragma unroll
            for (int q=0;q<8;q++){
                ulonglong2 w = sQ2[k2*32 + rb*8 + q];
                fma2(acc[q], xlo, w.x);
                fma2(acc[q], xhi, w.y);
            }
        }
        #pragma unroll
        for (int q=0;q<8;q++){
            float vlo, vhi;
            up2(acc[q], vlo, vhi);
            int r = rb*16 + 2*q;
            vlo = fmaxf(vlo, 0.f); vhi = fmaxf(vhi, 0.f);
            #pragma unroll
            for (int o=0;o<4;o++)
                p[o] += vlo*sW2[o*64 + r] + vhi*sW2[o*64 + r + 1];
        }
    }
    *(float4*)&outp[OUT_OFF + n*4] = make_float4(p[0]+b2[0], p[1]+b2[1], p[2]+b2[2], p[3]+b2[3]);
}

extern "C" void kernel_launch(void* const* d_in, const int* in_sizes, int n_in,
                              void* d_out, int out_size){
    (void)in_sizes; (void)n_in; (void)out_size;
    const float* x    = (const float*)d_in[0];
    const int*   ei   = (const int*)  d_in[1];
    const float* ea   = (const float*)d_in[2];
    const float* hnh  = (const float*)d_in[3];
    const float* hnc  = (const float*)d_in[4];
    const float* heh  = (const float*)d_in[5];
    const float* hec  = (const float*)d_in[6];
    const float* nWih = (const float*)d_in[7];
    const float* nWhh = (const float*)d_in[8];
    const float* nb   = (const float*)d_in[9];
    const float* eWih = (const float*)d_in[10];
    const float* eWhh = (const float*)d_in[11];
    const float* eb   = (const float*)d_in[12];
    const float* gatW = (const float*)d_in[13];
    const float* attS = (const float*)d_in[14];
    const float* attD = (const float*)d_in[15];
    const float* gatB = (const float*)d_in[16];
    const float* emW1 = (const float*)d_in[17];
    const float* emb1 = (const float*)d_in[18];
    const float* emW2 = (const float*)d_in[19];
    const float* emb2 = (const float*)d_in[20];
    const float* nmW1 = (const float*)d_in[21];
    const float* nmb1 = (const float*)d_in[22];
    const float* nmW2 = (const float*)d_in[23];
    const float* nmb2 = (const float*)d_in[24];
    float* out = (float*)d_out;

    static const int elstm_smem = (4480 + 4*4096)*4;             // 83456
    static const int nlstm_smem = (16384 + 1280 + 256)*4;        // 71680
    static const int gproj_smem = (24576 + 512)*4;               // 100352
    static const int emlp_smem  = 8192*4;                        // 32768

    static bool init_done = false;
    static cudaStream_t sB;
    static cudaEvent_t evFork, evCSR, evJoin;
    if (!init_done){
        cudaFuncSetAttribute(k_edge_lstm, cudaFuncAttributeMaxDynamicSharedMemorySize, elstm_smem);
        cudaFuncSetAttribute(k_node_lstm, cudaFuncAttributeMaxDynamicSharedMemorySize, nlstm_smem);
        cudaFuncSetAttribute(k_gat_proj,  cudaFuncAttributeMaxDynamicSharedMemorySize, gproj_smem);
        cudaFuncSetAttribute(k_edge_mlp,  cudaFuncAttributeMaxDynamicSharedMemorySize, emlp_smem);
        cudaStreamCreateWithFlags(&sB, cudaStreamNonBlocking);
        cudaEventCreateWithFlags(&evFork, cudaEventDisableTiming);
        cudaEventCreateWithFlags(&evCSR,  cudaEventDisableTiming);
        cudaEventCreateWithFlags(&evJoin, cudaEventDisableTiming);
        init_done = true;
    }

    // fork side stream B off the origin stream
    cudaEventRecord(evFork, 0);
    cudaStreamWaitEvent(sB, evFork, 0);

    // stream B: CSR build + node LSTM (independent of edge LSTM)
    k_zero_cnt<<<NBLK, 256, 0, sB>>>();
    k_count<<<(Ee+255)/256, 256, 0, sB>>>(ei);
    k_scan1<<<NBLK, 256, 0, sB>>>();

    // origin stream: edge LSTM (ncu capture slot)
    k_edge_lstm<<<(Ee/64 + 3)/4, 128, elstm_smem>>>(ea, heh, hec, eWih, eWhh, eb, out);

    k_scan2<<<1, 256, 0, sB>>>();
    k_scan3<<<NBLK, 256, 0, sB>>>();
    k_bin<<<(Ee+255)/256, 256, 0, sB>>>(ei);
    cudaEventRecord(evCSR, sB);
    k_node_lstm<<<(Nn+127)/128, 128, nlstm_smem, sB>>>(x, hnh, hnc, nWih, nWhh, nb, out);
    cudaEventRecord(evJoin, sB);

    // origin: enc_gather needs eh (origin) + CSR (evCSR) — overlaps node_lstm
    cudaStreamWaitEvent(0, evCSR, 0);
    k_enc_gather<<<(Nn+7)/8, 256>>>(out);

    // join, then serial tail on origin stream
    cudaStreamWaitEvent(0, evJoin, 0);
    k_gat_proj<<<(Nn+127)/128, 128, gproj_smem>>>(gatW, attS, attD);
    k_gat_fused<<<(Nn+7)/8, 256>>>(gatB);
    k_pq<<<(Nn+255)/256, 256>>>(emW1, emb1);
    k_edge_mlp<<<(Ee+127)/128, 256, emlp_smem>>>(ei, ea, emW1, emW2, emb2);
    k_agg_gather<<<(Nn+7)/8, 256>>>();
    k_node_mlp<<<(Nn+127)/128, 128>>>(nmW1, nmb1, nmW2, nmb2, out);
}